// round 3
// baseline (speedup 1.0000x reference)
#include <cuda_runtime.h>
#include <cstdint>

#define BB 8
#define LL 1024
#define DD 1024
#define HH 16
#define DKK 64
#define DI 4096
#define MTOK (BB*LL)
#define NREL 33

// ---------------- scratch (device globals; no allocation in kernel_launch) ----
__device__ float g_Q[MTOK*DD];
__device__ float g_K[MTOK*DD];
__device__ float g_V[MTOK*DD];
__device__ float g_Kt[BB*HH*DKK*LL];          // [bh][d][k]
__device__ float g_qrel[(size_t)MTOK*HH*NREL];
__device__ float g_S[(size_t)BB*HH*LL*LL];    // 512MB scores/probs
__device__ float g_arel[(size_t)BB*HH*LL*NREL];
__device__ float g_attnout[MTOK*DD];
__device__ float g_fc[MTOK*DD];
__device__ float g_x1[MTOK*DD];
__device__ float g_hid[(size_t)MTOK*DI];
__device__ float g_y[MTOK*DD];

// ---------------- generic strided/batched SGEMM ------------------------------
// EPI: 0 = (+bias if non-null), 1 = (+bias, relu), 2 = (acc + qrel[clip(col-row)]) * scale
template<int BM,int BN,int BK,int TM,int TN,int EPI>
__global__ void __launch_bounds__(256) bgemm_kernel(
    const float* __restrict__ A, const float* __restrict__ W,
    const float* __restrict__ bias, float* __restrict__ C,
    int M, int N, int K, int lda, int ldw, int ldc,
    long long sAb, long long sAh, long long sWb, long long sWh,
    long long sCb, long long sCh,
    const float* __restrict__ qrel, float scale)
{
    constexpr int NT = 256;
    int z = blockIdx.z;
    int b = z >> 4, h = z & 15;
    A += (size_t)b * sAb + (size_t)h * sAh;
    W += (size_t)b * sWb + (size_t)h * sWh;
    C += (size_t)b * sCb + (size_t)h * sCh;

    __shared__ float As[BK][BM];
    __shared__ float Bs[BK][BN];
    int tid = threadIdx.x;
    int brow = blockIdx.y * BM;
    int bcol = blockIdx.x * BN;
    int tm = (tid / (BN / TN)) * TM;
    int tn = (tid % (BN / TN)) * TN;

    float acc[TM][TN];
#pragma unroll
    for (int i = 0; i < TM; i++)
#pragma unroll
        for (int j = 0; j < TN; j++) acc[i][j] = 0.f;

    constexpr int AF4 = BM * BK / (NT * 4);
    constexpr int BF4 = BK * BN / (NT * 4);
    constexpr int AK4 = BK / 4;
    constexpr int BN4 = BN / 4;

    for (int k0 = 0; k0 < K; k0 += BK) {
#pragma unroll
        for (int i = 0; i < AF4; i++) {
            int id = tid + i * NT;
            int r = id / AK4;
            int c = (id % AK4) * 4;
            float4 v4 = *(const float4*)(A + (size_t)(brow + r) * lda + k0 + c);
            As[c + 0][r] = v4.x; As[c + 1][r] = v4.y;
            As[c + 2][r] = v4.z; As[c + 3][r] = v4.w;
        }
#pragma unroll
        for (int i = 0; i < BF4; i++) {
            int id = tid + i * NT;
            int r = id / BN4;
            int c = (id % BN4) * 4;
            *(float4*)&Bs[r][c] = *(const float4*)(W + (size_t)(k0 + r) * ldw + bcol + c);
        }
        __syncthreads();
#pragma unroll
        for (int kk = 0; kk < BK; kk++) {
            float a[TM], bb[TN];
#pragma unroll
            for (int i = 0; i < TM; i += 4) *(float4*)&a[i] = *(float4*)&As[kk][tm + i];
#pragma unroll
            for (int j = 0; j < TN; j += 4) *(float4*)&bb[j] = *(float4*)&Bs[kk][tn + j];
#pragma unroll
            for (int i = 0; i < TM; i++)
#pragma unroll
                for (int j = 0; j < TN; j++)
                    acc[i][j] = fmaf(a[i], bb[j], acc[i][j]);
        }
        __syncthreads();
    }

#pragma unroll
    for (int i = 0; i < TM; i++) {
        int row = brow + tm + i;
#pragma unroll
        for (int j = 0; j < TN; j += 4) {
            float4 o;
            float* po = &o.x;
#pragma unroll
            for (int jj = 0; jj < 4; jj++) {
                int col = bcol + tn + j + jj;
                float vv = acc[i][j + jj];
                if (EPI == 0) {
                    if (bias) vv += bias[col];
                } else if (EPI == 1) {
                    vv = fmaxf(vv + bias[col], 0.f);
                } else { // EPI == 2 : scores epilogue
                    int dist = col - row;
                    dist = dist < -16 ? -16 : (dist > 16 ? 16 : dist);
                    vv = (vv + qrel[((size_t)((b << 10) + row) * 16 + h) * 33 + (dist + 16)]) * scale;
                }
                po[jj] = vv;
            }
            *(float4*)(C + (size_t)row * ldc + bcol + tn + j) = o;
        }
    }
}

// ---------------- K repack: [b,l, h*64+d] -> [bh][d][l] -----------------------
__global__ void transpose_k_kernel(const float* __restrict__ Kmat, float* __restrict__ Kt)
{
    __shared__ float t[32][33];
    int bh = blockIdx.z; int b = bh >> 4, h = bh & 15;
    int k0 = blockIdx.x * 32, d0 = blockIdx.y * 32;
    for (int i = threadIdx.y; i < 32; i += 8)
        t[i][threadIdx.x] = Kmat[(size_t)(b * LL + k0 + i) * DD + h * DKK + d0 + threadIdx.x];
    __syncthreads();
    for (int i = threadIdx.y; i < 32; i += 8)
        Kt[((size_t)bh * DKK + d0 + i) * LL + k0 + threadIdx.x] = t[threadIdx.x][i];
}

// ---------------- qrel[b,l,h,r] = Qh[b,l,h,:] . rel_k[r,:] --------------------
__global__ void qrel_kernel(const float* __restrict__ Q, const float* __restrict__ rel_k,
                            float* __restrict__ qrel)
{
    __shared__ float rk[NREL * DKK];
    int t = threadIdx.x;
    for (int i = t; i < NREL * DKK; i += 256) rk[i] = rel_k[i];
    __syncthreads();
    int w = t >> 5, lane = t & 31;
    int item = blockIdx.x * 8 + w;     // item = (b*L + l)*16 + h
    int bl = item >> 4, h = item & 15;
    float q0 = Q[(size_t)bl * DD + h * DKK + lane * 2];
    float q1 = Q[(size_t)bl * DD + h * DKK + lane * 2 + 1];
    for (int r = 0; r < NREL; r++) {
        float v = q0 * rk[r * DKK + lane * 2] + q1 * rk[r * DKK + lane * 2 + 1];
        v += __shfl_xor_sync(0xffffffffu, v, 16);
        v += __shfl_xor_sync(0xffffffffu, v, 8);
        v += __shfl_xor_sync(0xffffffffu, v, 4);
        v += __shfl_xor_sync(0xffffffffu, v, 2);
        v += __shfl_xor_sync(0xffffffffu, v, 1);
        if (lane == 0) qrel[(size_t)item * NREL + r] = v;
    }
}

// ---------------- softmax (in-place) + 33-bin relative sums -------------------
__global__ void softmax_kernel(float* __restrict__ S, float* __restrict__ arel)
{
    int q = blockIdx.x, bh = blockIdx.y;
    float* row = S + ((size_t)bh * LL + q) * LL;
    int t = threadIdx.x;
    __shared__ float red[256];
    __shared__ float bins[NREL];
    if (t < NREL) bins[t] = 0.f;
    float v[4];
    float m = -1e30f;
#pragma unroll
    for (int i = 0; i < 4; i++) { v[i] = row[t + 256 * i]; m = fmaxf(m, v[i]); }
    red[t] = m; __syncthreads();
    for (int s = 128; s > 0; s >>= 1) { if (t < s) red[t] = fmaxf(red[t], red[t + s]); __syncthreads(); }
    m = red[0];
    __syncthreads();
    float s = 0.f;
#pragma unroll
    for (int i = 0; i < 4; i++) { v[i] = __expf(v[i] - m); s += v[i]; }
    red[t] = s; __syncthreads();
    for (int st = 128; st > 0; st >>= 1) { if (t < st) red[t] += red[t + st]; __syncthreads(); }
    float inv = 1.f / red[0];
#pragma unroll
    for (int i = 0; i < 4; i++) {
        float p = v[i] * inv;
        row[t + 256 * i] = p;
        int dist = (t + 256 * i) - q;
        dist = dist < -16 ? -16 : (dist > 16 ? 16 : dist);
        atomicAdd(&bins[dist + 16], p);
    }
    __syncthreads();
    if (t < NREL) arel[((size_t)bh * LL + q) * NREL + t] = bins[t];
}

// ---------------- attnout += arel @ rel_v (rank-33 update) --------------------
__global__ void addrel_kernel(float* __restrict__ attnout, const float* __restrict__ arel,
                              const float* __restrict__ rel_v)
{
    __shared__ float rv[NREL * DKK];
    int t = threadIdx.x;
    for (int i = t; i < NREL * DKK; i += 256) rv[i] = rel_v[i];
    __syncthreads();
    int bh = blockIdx.y; int b = bh >> 4, h = bh & 15;
    int q = blockIdx.x * 4 + t / 64;
    int dd = t % 64;
    const float* ar = arel + ((size_t)bh * LL + q) * NREL;
    float sum = 0.f;
#pragma unroll
    for (int r = 0; r < NREL; r++) sum = fmaf(ar[r], rv[r * DKK + dd], sum);
    attnout[(size_t)(b * LL + q) * DD + h * DKK + dd] += sum;
}

// ---------------- residual add + layernorm ------------------------------------
__global__ void ln_kernel(const float* __restrict__ X, const float* __restrict__ R,
                          const float* __restrict__ g, const float* __restrict__ be,
                          float* __restrict__ out)
{
    int row = blockIdx.x, t = threadIdx.x;
    __shared__ float red[256];
    float v[4];
    float s1 = 0.f;
#pragma unroll
    for (int i = 0; i < 4; i++) {
        int c = t + 256 * i;
        v[i] = X[(size_t)row * DD + c] + R[(size_t)row * DD + c];
        s1 += v[i];
    }
    red[t] = s1; __syncthreads();
    for (int s = 128; s > 0; s >>= 1) { if (t < s) red[t] += red[t + s]; __syncthreads(); }
    float mu = red[0] * (1.f / 1024.f);
    __syncthreads();
    float s2 = 0.f;
#pragma unroll
    for (int i = 0; i < 4; i++) { float d = v[i] - mu; s2 += d * d; }
    red[t] = s2; __syncthreads();
    for (int s = 128; s > 0; s >>= 1) { if (t < s) red[t] += red[t + s]; __syncthreads(); }
    float rstd = rsqrtf(red[0] * (1.f / 1024.f) + 1e-6f);
#pragma unroll
    for (int i = 0; i < 4; i++) {
        int c = t + 256 * i;
        out[(size_t)row * DD + c] = (v[i] - mu) * rstd * g[c] + be[c];
    }
}

// ---------------- launch ------------------------------------------------------
extern "C" void kernel_launch(void* const* d_in, const int* in_sizes, int n_in,
                              void* d_out, int out_size)
{
    const float* q    = (const float*)d_in[0];
    const float* k    = (const float*)d_in[1];
    const float* v    = (const float*)d_in[2];
    const float* wq   = (const float*)d_in[3];
    const float* bq   = (const float*)d_in[4];
    const float* wk   = (const float*)d_in[5];
    const float* bk   = (const float*)d_in[6];
    const float* wv   = (const float*)d_in[7];
    const float* bv   = (const float*)d_in[8];
    const float* wfc  = (const float*)d_in[9];
    const float* bfc  = (const float*)d_in[10];
    const float* w1   = (const float*)d_in[11];
    const float* b1   = (const float*)d_in[12];
    const float* w2   = (const float*)d_in[13];
    const float* b2   = (const float*)d_in[14];
    const float* ln_g = (const float*)d_in[15];
    const float* ln_b = (const float*)d_in[16];
    const float* rel_k= (const float*)d_in[17];
    const float* rel_v= (const float*)d_in[18];
    float* out = (float*)d_out;

    float *gQ, *gK, *gV, *gKt, *gqrel, *gS, *garel, *gattn, *gfc, *gx1, *ghid, *gy;
    cudaGetSymbolAddress((void**)&gQ, g_Q);
    cudaGetSymbolAddress((void**)&gK, g_K);
    cudaGetSymbolAddress((void**)&gV, g_V);
    cudaGetSymbolAddress((void**)&gKt, g_Kt);
    cudaGetSymbolAddress((void**)&gqrel, g_qrel);
    cudaGetSymbolAddress((void**)&gS, g_S);
    cudaGetSymbolAddress((void**)&garel, g_arel);
    cudaGetSymbolAddress((void**)&gattn, g_attnout);
    cudaGetSymbolAddress((void**)&gfc, g_fc);
    cudaGetSymbolAddress((void**)&gx1, g_x1);
    cudaGetSymbolAddress((void**)&ghid, g_hid);
    cudaGetSymbolAddress((void**)&gy, g_y);

    const long long LD = (long long)LL * DD;       // 1048576
    const long long L2 = (long long)LL * LL;       // 1048576

    // 1) projections
    bgemm_kernel<128,128,16,8,8,0><<<dim3(8,64,1),256>>>(q, wq, bq, gQ, MTOK,DD,DD, DD,DD,DD, 0,0,0,0,0,0, nullptr, 1.f);
    bgemm_kernel<128,128,16,8,8,0><<<dim3(8,64,1),256>>>(k, wk, bk, gK, MTOK,DD,DD, DD,DD,DD, 0,0,0,0,0,0, nullptr, 1.f);
    bgemm_kernel<128,128,16,8,8,0><<<dim3(8,64,1),256>>>(v, wv, bv, gV, MTOK,DD,DD, DD,DD,DD, 0,0,0,0,0,0, nullptr, 1.f);

    // 2) K repack + qrel
    transpose_k_kernel<<<dim3(32,2,BB*HH), dim3(32,8)>>>(gK, gKt);
    qrel_kernel<<<MTOK*HH/8, 256>>>(gQ, rel_k, gqrel);

    // 3) scores = (Qh Kh^T + qrel) / 8   (batched over bh, K=64)
    bgemm_kernel<128,128,16,8,8,2><<<dim3(8,8,BB*HH),256>>>(
        gQ, gKt, nullptr, gS, LL,LL,DKK, DD,LL,LL,
        LD, DKK, 16LL*DKK*LL, (long long)DKK*LL, 16LL*L2, L2, gqrel, 0.125f);

    // 4) softmax + relative bins (in place)
    softmax_kernel<<<dim3(LL, BB*HH), 256>>>(gS, garel);

    // 5) attnout = attn @ Vh ; += arel @ rel_v
    bgemm_kernel<128,64,16,8,4,0><<<dim3(1,8,BB*HH),256>>>(
        gS, gV, nullptr, gattn, LL,DKK,LL, LL,DD,DD,
        16LL*L2, L2, LD, DKK, LD, DKK, nullptr, 1.f);
    addrel_kernel<<<dim3(LL/4, BB*HH), 256>>>(gattn, garel, rel_v);

    // 6) fc + residual(q) + LN
    bgemm_kernel<128,128,16,8,8,0><<<dim3(8,64,1),256>>>(gattn, wfc, bfc, gfc, MTOK,DD,DD, DD,DD,DD, 0,0,0,0,0,0, nullptr, 1.f);
    ln_kernel<<<MTOK,256>>>(gfc, q, ln_g, ln_b, gx1);

    // 7) FFN + residual + LN -> out
    bgemm_kernel<128,128,16,8,8,1><<<dim3(32,64,1),256>>>(gx1, w1, b1, ghid, MTOK,DI,DD, DD,DI,DI, 0,0,0,0,0,0, nullptr, 1.f);
    bgemm_kernel<128,128,16,8,8,0><<<dim3(8,64,1),256>>>(ghid, w2, b2, gy, MTOK,DD,DI, DI,DD,DD, 0,0,0,0,0,0, nullptr, 1.f);
    ln_kernel<<<MTOK,256>>>(gy, gx1, ln_g, ln_b, out);
}

// round 5
// speedup vs baseline: 1.4038x; 1.4038x over previous
#include <cuda_runtime.h>
#include <cuda_bf16.h>
#include <cstdint>

#define BB 8
#define LL 1024
#define DD 1024
#define HH 16
#define DKK 64
#define DI 4096
#define MTOK (BB*LL)
#define NREL 33

using bf16 = __nv_bfloat16;

// ---------------- scratch (device globals) -----------------------------------
__device__ float g_Q[MTOK*DD];
__device__ float g_K[MTOK*DD];
__device__ float g_V[MTOK*DD];
__device__ float g_qrel[(size_t)MTOK*HH*NREL];
__device__ float g_S[(size_t)BB*HH*LL*LL];    // 512MB scores/probs
__device__ float g_arel[(size_t)BB*HH*LL*NREL];
__device__ float g_attnout[MTOK*DD];
__device__ float g_fc[MTOK*DD];
__device__ float g_x1[MTOK*DD];
__device__ float g_hid[(size_t)MTOK*DI];
__device__ float g_y[MTOK*DD];

// bf16 split operands (B-side of GEMMs)
__device__ bf16 g_wqt_h[DD*DD],  g_wqt_l[DD*DD];
__device__ bf16 g_wkt_h[DD*DD],  g_wkt_l[DD*DD];
__device__ bf16 g_wvt_h[DD*DD],  g_wvt_l[DD*DD];
__device__ bf16 g_wft_h[DD*DD],  g_wft_l[DD*DD];
__device__ bf16 g_w1t_h[(size_t)DI*DD], g_w1t_l[(size_t)DI*DD];
__device__ bf16 g_w2t_h[(size_t)DD*DI], g_w2t_l[(size_t)DD*DI];
__device__ bf16 g_Kb_h[MTOK*DD], g_Kb_l[MTOK*DD];           // split of K proj (same layout)
__device__ bf16 g_Vt_h[BB*HH*DKK*LL], g_Vt_l[BB*HH*DKK*LL]; // [bh][d][l]

// ---------------- helpers -----------------------------------------------------
__device__ __forceinline__ uint32_t smem_u32(const void* p) {
    uint32_t a;
    asm("{ .reg .u64 t; cvta.to.shared.u64 t, %1; cvt.u32.u64 %0, t; }" : "=r"(a) : "l"(p));
    return a;
}
__device__ __forceinline__ uint32_t pk2(bf16 a, bf16 b) {
    __nv_bfloat162 t = __halves2bfloat162(a, b);
    return *reinterpret_cast<uint32_t*>(&t);
}
__device__ __forceinline__ void bsplit(float x, bf16& h, bf16& l) {
    h = __float2bfloat16(x);
    l = __float2bfloat16(x - __bfloat162float(h));
}
__device__ __forceinline__ void ldsm4(uint32_t* r, uint32_t addr) {
    asm volatile("ldmatrix.sync.aligned.m8n8.x4.shared.b16 {%0,%1,%2,%3}, [%4];"
                 : "=r"(r[0]), "=r"(r[1]), "=r"(r[2]), "=r"(r[3]) : "r"(addr));
}
__device__ __forceinline__ void mma16816(float* d, const uint32_t* a, const uint32_t* b) {
    asm volatile("mma.sync.aligned.m16n8k16.row.col.f32.bf16.bf16.f32 "
                 "{%0,%1,%2,%3}, {%4,%5,%6,%7}, {%8,%9}, {%0,%1,%2,%3};"
                 : "+f"(d[0]), "+f"(d[1]), "+f"(d[2]), "+f"(d[3])
                 : "r"(a[0]), "r"(a[1]), "r"(a[2]), "r"(a[3]), "r"(b[0]), "r"(b[1]));
}

// ---------------- mma.sync split-bf16 batched GEMM ----------------------------
// C[row, col] = sum_k A[row,k] * Bt[col,k]     (A fp32, Bt pre-split bf16 hi/lo)
// EPI: 0 = (+bias if non-null), 1 = (+bias, relu), 2 = (acc + qrel[clip]) * scale
template<int BN, int EPI>
__global__ void __launch_bounds__(256, 1) mma_gemm(
    const float* __restrict__ A,
    const bf16* __restrict__ Bhi, const bf16* __restrict__ Blo,
    const float* __restrict__ bias, float* __restrict__ C,
    int K, int lda, int ldb, int ldc,
    long long sAb, long long sAh, long long sBb, long long sBh,
    long long sCb, long long sCh,
    const float* __restrict__ qrel, float scale)
{
    constexpr int NT = BN / 16;   // n8-tiles per warp (warp covers BN/2 cols)
    constexpr int BI = BN / 64;   // 16B B-chunks per thread per operand

    __shared__ __align__(16) bf16 sAhi[128 * 40];
    __shared__ __align__(16) bf16 sAlo[128 * 40];
    __shared__ __align__(16) bf16 sBhi[BN * 40];
    __shared__ __align__(16) bf16 sBlo[BN * 40];

    int z = blockIdx.z, b = z >> 4, h = z & 15;
    A   += (size_t)b * sAb + (size_t)h * sAh;
    Bhi += (size_t)b * sBb + (size_t)h * sBh;
    Blo += (size_t)b * sBb + (size_t)h * sBh;
    C   += (size_t)b * sCb + (size_t)h * sCh;

    int tid = threadIdx.x, wid = tid >> 5, lane = tid & 31;
    int brow = blockIdx.y * 128;
    int bcol = blockIdx.x * BN;
    int wm = (wid & 3) * 32;
    int wn = (wid >> 2) * (BN / 2);

    uint32_t uAhi = smem_u32(sAhi), uAlo = smem_u32(sAlo);
    uint32_t uBhi = smem_u32(sBhi), uBlo = smem_u32(sBlo);

    float acc[2][NT][4];
#pragma unroll
    for (int mt = 0; mt < 2; mt++)
#pragma unroll
        for (int nt = 0; nt < NT; nt++)
#pragma unroll
            for (int i = 0; i < 4; i++) acc[mt][nt][i] = 0.f;

    const int KT = K >> 5;
    float4 aR[4];
    uint4 bhR[BI], blR[BI];

#define LOAD_TILE_REGS(k0) do {                                                   \
    _Pragma("unroll")                                                             \
    for (int i = 0; i < 4; i++) {                                                 \
        int id = i * 256 + tid; int r = id >> 3, c = (id & 7) << 2;               \
        aR[i] = *(const float4*)(A + (size_t)(brow + r) * lda + (k0) + c);        \
    }                                                                             \
    _Pragma("unroll")                                                             \
    for (int i = 0; i < BI; i++) {                                                \
        int id = i * 256 + tid; int r = id >> 2, c = (id & 3) << 3;               \
        size_t g = (size_t)(bcol + r) * ldb + (k0) + c;                           \
        bhR[i] = *(const uint4*)(Bhi + g);                                        \
        blR[i] = *(const uint4*)(Blo + g);                                        \
    }                                                                             \
} while (0)

#define STORE_TILE_SMEM() do {                                                    \
    _Pragma("unroll")                                                             \
    for (int i = 0; i < 4; i++) {                                                 \
        int id = i * 256 + tid; int r = id >> 3, c4 = id & 7;                     \
        bf16 h0, h1, h2, h3, l0, l1, l2, l3;                                      \
        bsplit(aR[i].x, h0, l0); bsplit(aR[i].y, h1, l1);                         \
        bsplit(aR[i].z, h2, l2); bsplit(aR[i].w, h3, l3);                         \
        *(uint2*)&sAhi[r * 40 + c4 * 4] = make_uint2(pk2(h0, h1), pk2(h2, h3));   \
        *(uint2*)&sAlo[r * 40 + c4 * 4] = make_uint2(pk2(l0, l1), pk2(l2, l3));   \
    }                                                                             \
    _Pragma("unroll")                                                             \
    for (int i = 0; i < BI; i++) {                                                \
        int id = i * 256 + tid; int r = id >> 2, c = (id & 3) << 3;               \
        *(uint4*)&sBhi[r * 40 + c] = bhR[i];                                      \
        *(uint4*)&sBlo[r * 40 + c] = blR[i];                                      \
    }                                                                             \
} while (0)

    LOAD_TILE_REGS(0);

    for (int kt = 0; kt < KT; kt++) {
        if (kt > 0) __syncthreads();
        STORE_TILE_SMEM();
        __syncthreads();
        if (kt + 1 < KT) LOAD_TILE_REGS((kt + 1) << 5);

#pragma unroll
        for (int ks = 0; ks < 2; ks++) {
            uint32_t aH[2][4], aL[2][4], bH[NT][2], bL[NT][2];
#pragma unroll
            for (int mt = 0; mt < 2; mt++) {
                uint32_t ar = wm + mt * 16 + (lane & 15);
                uint32_t ac = ks * 16 + ((lane >> 4) << 3);
                uint32_t off = (ar * 40 + ac) * 2;
                ldsm4(aH[mt], uAhi + off);
                ldsm4(aL[mt], uAlo + off);
            }
#pragma unroll
            for (int p = 0; p < NT / 2; p++) {
                uint32_t br = wn + p * 16 + ((lane >> 4) << 3) + (lane & 7);
                uint32_t bc = ks * 16 + (((lane >> 3) & 1) << 3);
                uint32_t off = (br * 40 + bc) * 2;
                uint32_t r[4];
                ldsm4(r, uBhi + off);
                bH[p * 2][0] = r[0]; bH[p * 2][1] = r[1];
                bH[p * 2 + 1][0] = r[2]; bH[p * 2 + 1][1] = r[3];
                ldsm4(r, uBlo + off);
                bL[p * 2][0] = r[0]; bL[p * 2][1] = r[1];
                bL[p * 2 + 1][0] = r[2]; bL[p * 2 + 1][1] = r[3];
            }
#pragma unroll
            for (int mt = 0; mt < 2; mt++)
#pragma unroll
                for (int nt = 0; nt < NT; nt++) {
                    mma16816(acc[mt][nt], aH[mt], bH[nt]);   // hi*hi
                    mma16816(acc[mt][nt], aH[mt], bL[nt]);   // hi*lo
                    mma16816(acc[mt][nt], aL[mt], bH[nt]);   // lo*hi
                }
        }
    }

    // epilogue: fragment c0,c1 -> (row, col/col+1), c2,c3 -> (row+8, ...)
#pragma unroll
    for (int mt = 0; mt < 2; mt++) {
#pragma unroll
        for (int nt = 0; nt < NT; nt++) {
            int r0 = brow + wm + mt * 16 + (lane >> 2);
            int c0 = bcol + wn + nt * 8 + ((lane & 3) << 1);
#pragma unroll
            for (int half = 0; half < 2; half++) {
                int row = r0 + half * 8;
                float v0 = acc[mt][nt][half * 2 + 0];
                float v1 = acc[mt][nt][half * 2 + 1];
                if (EPI == 0) {
                    if (bias) { v0 += bias[c0]; v1 += bias[c0 + 1]; }
                } else if (EPI == 1) {
                    v0 = fmaxf(v0 + bias[c0], 0.f);
                    v1 = fmaxf(v1 + bias[c0 + 1], 0.f);
                } else {
                    const float* qr = qrel + ((size_t)((b << 10) + row) * 16 + h) * 33;
                    int d0 = c0 - row;     d0 = d0 < -16 ? -16 : (d0 > 16 ? 16 : d0);
                    int d1 = c0 + 1 - row; d1 = d1 < -16 ? -16 : (d1 > 16 ? 16 : d1);
                    v0 = (v0 + qr[d0 + 16]) * scale;
                    v1 = (v1 + qr[d1 + 16]) * scale;
                }
                *(float2*)(C + (size_t)row * ldc + c0) = make_float2(v0, v1);
            }
        }
    }
#undef LOAD_TILE_REGS
#undef STORE_TILE_SMEM
}

// ---------------- W [K,N] fp32 -> Wt [N,K] bf16 hi/lo -------------------------
__global__ void convert_wt_kernel(const float* __restrict__ W, bf16* __restrict__ hi,
                                  bf16* __restrict__ lo, int K, int N)
{
    __shared__ float t[32][33];
    int n0 = blockIdx.x * 32, k0 = blockIdx.y * 32;
    int tx = threadIdx.x, ty = threadIdx.y;
    for (int i = ty; i < 32; i += 8)
        t[i][tx] = W[(size_t)(k0 + i) * N + n0 + tx];
    __syncthreads();
    for (int i = ty; i < 32; i += 8) {
        float x = t[tx][i];                          // = W[k0+tx][n0+i]
        bf16 h, l; bsplit(x, h, l);
        size_t o = (size_t)(n0 + i) * K + k0 + tx;
        hi[o] = h; lo[o] = l;
    }
}

// ---------------- elementwise fp32 -> bf16 hi/lo (same layout) ----------------
__global__ void split_kernel(const float* __restrict__ X, bf16* __restrict__ hi,
                             bf16* __restrict__ lo)
{
    size_t i = ((size_t)blockIdx.x * 256 + threadIdx.x) * 4;
    float4 v = *(const float4*)(X + i);
    bf16 h0, h1, h2, h3, l0, l1, l2, l3;
    bsplit(v.x, h0, l0); bsplit(v.y, h1, l1);
    bsplit(v.z, h2, l2); bsplit(v.w, h3, l3);
    *(uint2*)(hi + i) = make_uint2(pk2(h0, h1), pk2(h2, h3));
    *(uint2*)(lo + i) = make_uint2(pk2(l0, l1), pk2(l2, l3));
}

// ---------------- V: [b,l,h*64+d] -> Vt [bh][d][l] bf16 hi/lo -----------------
__global__ void transpose_split_v(const float* __restrict__ V, bf16* __restrict__ hi,
                                  bf16* __restrict__ lo)
{
    __shared__ float t[32][33];
    int bh = blockIdx.z; int b = bh >> 4, h = bh & 15;
    int l0 = blockIdx.x * 32, d0 = blockIdx.y * 32;
    for (int i = threadIdx.y; i < 32; i += 8)
        t[i][threadIdx.x] = V[(size_t)(b * LL + l0 + i) * DD + h * DKK + d0 + threadIdx.x];
    __syncthreads();
    for (int i = threadIdx.y; i < 32; i += 8) {
        float x = t[threadIdx.x][i];
        bf16 hh, ll; bsplit(x, hh, ll);
        size_t o = ((size_t)bh * DKK + d0 + i) * LL + l0 + threadIdx.x;
        hi[o] = hh; lo[o] = ll;
    }
}

// ---------------- qrel[b,l,h,r] = Qh[b,l,h,:] . rel_k[r,:] --------------------
__global__ void qrel_kernel(const float* __restrict__ Q, const float* __restrict__ rel_k,
                            float* __restrict__ qrel)
{
    __shared__ float rk[NREL * DKK];
    int t = threadIdx.x;
    for (int i = t; i < NREL * DKK; i += 256) rk[i] = rel_k[i];
    __syncthreads();
    int w = t >> 5, lane = t & 31;
    int item = blockIdx.x * 8 + w;
    int bl = item >> 4, h = item & 15;
    float q0 = Q[(size_t)bl * DD + h * DKK + lane * 2];
    float q1 = Q[(size_t)bl * DD + h * DKK + lane * 2 + 1];
    for (int r = 0; r < NREL; r++) {
        float v = q0 * rk[r * DKK + lane * 2] + q1 * rk[r * DKK + lane * 2 + 1];
        v += __shfl_xor_sync(0xffffffffu, v, 16);
        v += __shfl_xor_sync(0xffffffffu, v, 8);
        v += __shfl_xor_sync(0xffffffffu, v, 4);
        v += __shfl_xor_sync(0xffffffffu, v, 2);
        v += __shfl_xor_sync(0xffffffffu, v, 1);
        if (lane == 0) qrel[(size_t)item * NREL + r] = v;
    }
}

// ---------------- softmax (in-place) + 33-bin relative sums -------------------
__global__ void softmax_kernel(float* __restrict__ S, float* __restrict__ arel)
{
    int q = blockIdx.x, bh = blockIdx.y;
    float* row = S + ((size_t)bh * LL + q) * LL;
    int t = threadIdx.x;
    __shared__ float red[256];
    __shared__ float bins[NREL];
    if (t < NREL) bins[t] = 0.f;
    float v[4];
    float m = -1e30f;
#pragma unroll
    for (int i = 0; i < 4; i++) { v[i] = row[t + 256 * i]; m = fmaxf(m, v[i]); }
    red[t] = m; __syncthreads();
    for (int s = 128; s > 0; s >>= 1) { if (t < s) red[t] = fmaxf(red[t], red[t + s]); __syncthreads(); }
    m = red[0];
    __syncthreads();
    float s = 0.f;
#pragma unroll
    for (int i = 0; i < 4; i++) { v[i] = __expf(v[i] - m); s += v[i]; }
    red[t] = s; __syncthreads();
    for (int st = 128; st > 0; st >>= 1) { if (t < st) red[t] += red[t + st]; __syncthreads(); }
    float inv = 1.f / red[0];
#pragma unroll
    for (int i = 0; i < 4; i++) {
        float p = v[i] * inv;
        row[t + 256 * i] = p;
        int dist = (t + 256 * i) - q;
        dist = dist < -16 ? -16 : (dist > 16 ? 16 : dist);
        atomicAdd(&bins[dist + 16], p);
    }
    __syncthreads();
    if (t < NREL) arel[((size_t)bh * LL + q) * NREL + t] = bins[t];
}

// ---------------- attnout += arel @ rel_v (rank-33 update) --------------------
__global__ void addrel_kernel(float* __restrict__ attnout, const float* __restrict__ arel,
                              const float* __restrict__ rel_v)
{
    __shared__ float rv[NREL * DKK];
    int t = threadIdx.x;
    for (int i = t; i < NREL * DKK; i += 256) rv[i] = rel_v[i];
    __syncthreads();
    int bh = blockIdx.y; int b = bh >> 4, h = bh & 15;
    int q = blockIdx.x * 4 + t / 64;
    int dd = t % 64;
    const float* ar = arel + ((size_t)bh * LL + q) * NREL;
    float sum = 0.f;
#pragma unroll
    for (int r = 0; r < NREL; r++) sum = fmaf(ar[r], rv[r * DKK + dd], sum);
    attnout[(size_t)(b * LL + q) * DD + h * DKK + dd] += sum;
}

// ---------------- residual add + layernorm ------------------------------------
__global__ void ln_kernel(const float* __restrict__ X, const float* __restrict__ R,
                          const float* __restrict__ g, const float* __restrict__ be,
                          float* __restrict__ out)
{
    int row = blockIdx.x, t = threadIdx.x;
    __shared__ float red[256];
    float v[4];
    float s1 = 0.f;
#pragma unroll
    for (int i = 0; i < 4; i++) {
        int c = t + 256 * i;
        v[i] = X[(size_t)row * DD + c] + R[(size_t)row * DD + c];
        s1 += v[i];
    }
    red[t] = s1; __syncthreads();
    for (int s = 128; s > 0; s >>= 1) { if (t < s) red[t] += red[t + s]; __syncthreads(); }
    float mu = red[0] * (1.f / 1024.f);
    __syncthreads();
    float s2 = 0.f;
#pragma unroll
    for (int i = 0; i < 4; i++) { float d = v[i] - mu; s2 += d * d; }
    red[t] = s2; __syncthreads();
    for (int s = 128; s > 0; s >>= 1) { if (t < s) red[t] += red[t + s]; __syncthreads(); }
    float rstd = rsqrtf(red[0] * (1.f / 1024.f) + 1e-6f);
#pragma unroll
    for (int i = 0; i < 4; i++) {
        int c = t + 256 * i;
        out[(size_t)row * DD + c] = (v[i] - mu) * rstd * g[c] + be[c];
    }
}

// ---------------- launch ------------------------------------------------------
extern "C" void kernel_launch(void* const* d_in, const int* in_sizes, int n_in,
                              void* d_out, int out_size)
{
    const float* q    = (const float*)d_in[0];
    const float* k    = (const float*)d_in[1];
    const float* v    = (const float*)d_in[2];
    const float* wq   = (const float*)d_in[3];
    const float* bq   = (const float*)d_in[4];
    const float* wk   = (const float*)d_in[5];
    const float* bk   = (const float*)d_in[6];
    const float* wv   = (const float*)d_in[7];
    const float* bv   = (const float*)d_in[8];
    const float* wfc  = (const float*)d_in[9];
    const float* bfc  = (const float*)d_in[10];
    const float* w1   = (const float*)d_in[11];
    const float* b1   = (const float*)d_in[12];
    const float* w2   = (const float*)d_in[13];
    const float* b2   = (const float*)d_in[14];
    const float* ln_g = (const float*)d_in[15];
    const float* ln_b = (const float*)d_in[16];
    const float* rel_k= (const float*)d_in[17];
    const float* rel_v= (const float*)d_in[18];
    float* out = (float*)d_out;

    float *gQ, *gK, *gV, *gqrel, *gS, *garel, *gattn, *gfc, *gx1, *ghid, *gy;
    cudaGetSymbolAddress((void**)&gQ, g_Q);
    cudaGetSymbolAddress((void**)&gK, g_K);
    cudaGetSymbolAddress((void**)&gV, g_V);
    cudaGetSymbolAddress((void**)&gqrel, g_qrel);
    cudaGetSymbolAddress((void**)&gS, g_S);
    cudaGetSymbolAddress((void**)&garel, g_arel);
    cudaGetSymbolAddress((void**)&gattn, g_attnout);
    cudaGetSymbolAddress((void**)&gfc, g_fc);
    cudaGetSymbolAddress((void**)&gx1, g_x1);
    cudaGetSymbolAddress((void**)&ghid, g_hid);
    cudaGetSymbolAddress((void**)&gy, g_y);

    bf16 *wqt_h,*wqt_l,*wkt_h,*wkt_l,*wvt_h,*wvt_l,*wft_h,*wft_l,*w1t_h,*w1t_l,*w2t_h,*w2t_l;
    bf16 *Kb_h,*Kb_l,*Vt_h,*Vt_l;
    cudaGetSymbolAddress((void**)&wqt_h, g_wqt_h); cudaGetSymbolAddress((void**)&wqt_l, g_wqt_l);
    cudaGetSymbolAddress((void**)&wkt_h, g_wkt_h); cudaGetSymbolAddress((void**)&wkt_l, g_wkt_l);
    cudaGetSymbolAddress((void**)&wvt_h, g_wvt_h); cudaGetSymbolAddress((void**)&wvt_l, g_wvt_l);
    cudaGetSymbolAddress((void**)&wft_h, g_wft_h); cudaGetSymbolAddress((void**)&wft_l, g_wft_l);
    cudaGetSymbolAddress((void**)&w1t_h, g_w1t_h); cudaGetSymbolAddress((void**)&w1t_l, g_w1t_l);
    cudaGetSymbolAddress((void**)&w2t_h, g_w2t_h); cudaGetSymbolAddress((void**)&w2t_l, g_w2t_l);
    cudaGetSymbolAddress((void**)&Kb_h, g_Kb_h);   cudaGetSymbolAddress((void**)&Kb_l, g_Kb_l);
    cudaGetSymbolAddress((void**)&Vt_h, g_Vt_h);   cudaGetSymbolAddress((void**)&Vt_l, g_Vt_l);

    const long long LD = (long long)LL * DD;
    const long long L2 = (long long)LL * LL;

    // 0) weight transpose + bf16 split
    convert_wt_kernel<<<dim3(32,32),   dim3(32,8)>>>(wq,  wqt_h, wqt_l, DD, DD);
    convert_wt_kernel<<<dim3(32,32),   dim3(32,8)>>>(wk,  wkt_h, wkt_l, DD, DD);
    convert_wt_kernel<<<dim3(32,32),   dim3(32,8)>>>(wv,  wvt_h, wvt_l, DD, DD);
    convert_wt_kernel<<<dim3(32,32),   dim3(32,8)>>>(wfc, wft_h, wft_l, DD, DD);
    convert_wt_kernel<<<dim3(128,32),  dim3(32,8)>>>(w1,  w1t_h, w1t_l, DD, DI);
    convert_wt_kernel<<<dim3(32,128),  dim3(32,8)>>>(w2,  w2t_h, w2t_l, DI, DD);

    // 1) projections (tensor core, split bf16)
    mma_gemm<128,0><<<dim3(8,64,1),256>>>(q, wqt_h, wqt_l, bq, gQ, DD, DD,DD,DD, 0,0,0,0,0,0, nullptr, 1.f);
    mma_gemm<128,0><<<dim3(8,64,1),256>>>(k, wkt_h, wkt_l, bk, gK, DD, DD,DD,DD, 0,0,0,0,0,0, nullptr, 1.f);
    mma_gemm<128,0><<<dim3(8,64,1),256>>>(v, wvt_h, wvt_l, bv, gV, DD, DD,DD,DD, 0,0,0,0,0,0, nullptr, 1.f);

    // 2) split K, transpose+split V, qrel
    split_kernel<<<MTOK*DD/(256*4), 256>>>(gK, Kb_h, Kb_l);
    transpose_split_v<<<dim3(32,2,BB*HH), dim3(32,8)>>>(gV, Vt_h, Vt_l);
    qrel_kernel<<<MTOK*HH/8, 256>>>(gQ, rel_k, gqrel);

    // 3) scores = (Qh Kh^T + qrel) / 8   (batched over bh, K=64)
    mma_gemm<128,2><<<dim3(8,8,BB*HH),256>>>(
        gQ, Kb_h, Kb_l, nullptr, gS, DKK, DD, DD, LL,
        LD, DKK, LD, DKK, 16LL*L2, L2, gqrel, 0.125f);

    // 4) softmax + relative bins (in place)
    softmax_kernel<<<dim3(LL, BB*HH), 256>>>(gS, garel);

    // 5) attnout = attn @ Vh (BN=64); += arel @ rel_v
    mma_gemm<64,0><<<dim3(1,8,BB*HH),256>>>(
        gS, Vt_h, Vt_l, nullptr, gattn, LL, LL, LL, DD,
        16LL*L2, L2, 16LL*(long long)DKK*LL, (long long)DKK*LL, LD, DKK, nullptr, 1.f);
    addrel_kernel<<<dim3(LL/4, BB*HH), 256>>>(gattn, garel, rel_v);

    // 6) fc + residual(q) + LN
    mma_gemm<128,0><<<dim3(8,64,1),256>>>(gattn, wft_h, wft_l, bfc, gfc, DD, DD,DD,DD, 0,0,0,0,0,0, nullptr, 1.f);
    ln_kernel<<<MTOK,256>>>(gfc, q, ln_g, ln_b, gx1);

    // 7) FFN + residual + LN -> out
    mma_gemm<128,1><<<dim3(32,64,1),256>>>(gx1, w1t_h, w1t_l, b1, ghid, DD, DD,DD,DI, 0,0,0,0,0,0, nullptr, 1.f);
    mma_gemm<128,0><<<dim3(8,64,1),256>>>(ghid, w2t_h, w2t_l, b2, gy, DI, DI,DI,DD, 0,0,0,0,0,0, nullptr, 1.f);
    ln_kernel<<<MTOK,256>>>(gy, gx1, ln_g, ln_b, out);
}

// round 8
// speedup vs baseline: 3.3764x; 2.4052x over previous
#include <cuda_runtime.h>
#include <cuda_bf16.h>
#include <cstdint>

#define BB 8
#define LL 1024
#define DD 1024
#define HH 16
#define DKK 64
#define DI 4096
#define MTOK (BB*LL)
#define NREL 33

using bf16 = __nv_bfloat16;

// ---------------- scratch (device globals) -----------------------------------
__device__ float g_V[MTOK*DD];
__device__ float g_qrel[(size_t)MTOK*HH*NREL];
__device__ float g_S[(size_t)BB*HH*LL*LL];    // 512MB scores
__device__ float g_arel[(size_t)BB*HH*LL*NREL];
__device__ float g_attnout[MTOK*DD];
__device__ float g_fc[MTOK*DD];
__device__ float g_x1[MTOK*DD];
__device__ float g_y[MTOK*DD];

// bf16 split operand pairs
__device__ bf16 g_wqt_h[DD*DD],  g_wqt_l[DD*DD];
__device__ bf16 g_wkt_h[DD*DD],  g_wkt_l[DD*DD];
__device__ bf16 g_wvt_h[DD*DD],  g_wvt_l[DD*DD];
__device__ bf16 g_wft_h[DD*DD],  g_wft_l[DD*DD];
__device__ bf16 g_w1t_h[(size_t)DI*DD], g_w1t_l[(size_t)DI*DD];
__device__ bf16 g_w2t_h[(size_t)DD*DI], g_w2t_l[(size_t)DD*DI];
__device__ bf16 g_qs_h[MTOK*DD], g_qs_l[MTOK*DD];       // input q split
__device__ bf16 g_ks_h[MTOK*DD], g_ks_l[MTOK*DD];       // input k split
__device__ bf16 g_vs_h[MTOK*DD], g_vs_l[MTOK*DD];       // input v split
__device__ bf16 g_Qs_h[MTOK*DD], g_Qs_l[MTOK*DD];       // Q proj split
__device__ bf16 g_Kb_h[MTOK*DD], g_Kb_l[MTOK*DD];       // K proj split
__device__ bf16 g_Vt_h[BB*HH*DKK*LL], g_Vt_l[BB*HH*DKK*LL]; // V proj [bh][d][l]
__device__ bf16 g_P_h[(size_t)BB*HH*LL*LL], g_P_l[(size_t)BB*HH*LL*LL]; // probs split
__device__ bf16 g_AT_h[MTOK*DD], g_AT_l[MTOK*DD];       // attn+rel split
__device__ bf16 g_x1s_h[MTOK*DD], g_x1s_l[MTOK*DD];     // LN1 out split
__device__ bf16 g_hid_h[(size_t)MTOK*DI], g_hid_l[(size_t)MTOK*DI]; // FFN hidden split

// ---------------- helpers -----------------------------------------------------
__device__ __forceinline__ uint32_t smem_u32(const void* p) {
    uint32_t a;
    asm("{ .reg .u64 t; cvta.to.shared.u64 t, %1; cvt.u32.u64 %0, t; }" : "=r"(a) : "l"(p));
    return a;
}
__device__ __forceinline__ uint32_t pk2(bf16 a, bf16 b) {
    __nv_bfloat162 t = __halves2bfloat162(a, b);
    return *reinterpret_cast<uint32_t*>(&t);
}
__device__ __forceinline__ void bsplit(float x, bf16& h, bf16& l) {
    h = __float2bfloat16(x);
    l = __float2bfloat16(x - __bfloat162float(h));
}
__device__ __forceinline__ void ldsm4(uint32_t* r, uint32_t addr) {
    asm volatile("ldmatrix.sync.aligned.m8n8.x4.shared.b16 {%0,%1,%2,%3}, [%4];"
                 : "=r"(r[0]), "=r"(r[1]), "=r"(r[2]), "=r"(r[3]) : "r"(addr));
}
__device__ __forceinline__ void mma16816(float* d, const uint32_t* a, const uint32_t* b) {
    asm volatile("mma.sync.aligned.m16n8k16.row.col.f32.bf16.bf16.f32 "
                 "{%0,%1,%2,%3}, {%4,%5,%6,%7}, {%8,%9}, {%0,%1,%2,%3};"
                 : "+f"(d[0]), "+f"(d[1]), "+f"(d[2]), "+f"(d[3])
                 : "r"(a[0]), "r"(a[1]), "r"(a[2]), "r"(a[3]), "r"(b[0]), "r"(b[1]));
}
__device__ __forceinline__ void cpa16(uint32_t s, const void* g) {
    asm volatile("cp.async.cg.shared.global [%0], [%1], 16;" :: "r"(s), "l"(g));
}
#define CP_COMMIT() asm volatile("cp.async.commit_group;" ::: "memory")
#define CP_WAIT1()  asm volatile("cp.async.wait_group 1;" ::: "memory")

// ---------------- mma.sync split-bf16 batched GEMM, 3-stage cp.async ----------
// C[row,col] = sum_k (Ahi+Alo)[row,k] * (Bhi+Blo)[col,k]  (3-term: hh+hl+lh)
// EPI: 0 = (+bias if non-null), 1 = (+bias, relu), 2 = (acc + qrel[clip]) * scale
// STORE: 0 = fp32 C, 1 = split Chi/Clo, 2 = both
template<int BN, int EPI, int STORE>
__global__ void __launch_bounds__(256, 1) mma_gemm(
    const bf16* __restrict__ Ahi, const bf16* __restrict__ Alo,
    const bf16* __restrict__ Bhi, const bf16* __restrict__ Blo,
    const float* __restrict__ bias, float* __restrict__ C,
    bf16* __restrict__ Chi, bf16* __restrict__ Clo,
    int K, int lda, int ldb, int ldc,
    long long sAb, long long sAh, long long sBb, long long sBh,
    long long sCb, long long sCh,
    const float* __restrict__ qrel, float scale)
{
    constexpr int NT = BN / 16;            // n8-tiles per warp
    constexpr int SSH = 10240 + 80 * BN;   // stage stride (halves): A 2*5120 + B 2*40*BN
    constexpr int SS2 = SSH * 2;           // bytes
    constexpr int ALO2 = 10240;            // byte offset of A-lo in stage
    constexpr int BHI2 = 20480;            // byte offset of B-hi
    constexpr int BLOD = BN * 80;          // B-lo rel offset (bytes)

    extern __shared__ __align__(16) char dsm[];
    uint32_t ubase = smem_u32(dsm);

    int z = blockIdx.z, b = z >> 4, h = z & 15;
    Ahi += (size_t)b * sAb + (size_t)h * sAh;
    Alo += (size_t)b * sAb + (size_t)h * sAh;
    Bhi += (size_t)b * sBb + (size_t)h * sBh;
    Blo += (size_t)b * sBb + (size_t)h * sBh;
    size_t coff = (size_t)b * sCb + (size_t)h * sCh;
    if (STORE != 1) C += coff;
    if (STORE >= 1) { Chi += coff; Clo += coff; }

    int tid = threadIdx.x, wid = tid >> 5, lane = tid & 31;
    int brow = blockIdx.y * 128;
    int bcol = blockIdx.x * BN;
    int wm = (wid & 3) * 32;
    int wn = (wid >> 2) * (BN / 2);

    float acc[2][NT][4];
#pragma unroll
    for (int mt = 0; mt < 2; mt++)
#pragma unroll
        for (int nt = 0; nt < NT; nt++)
#pragma unroll
            for (int i = 0; i < 4; i++) acc[mt][nt][i] = 0.f;

    const int KT = K >> 5;

#define ISSUE(stg, k0) do {                                                       \
    uint32_t us_ = ubase + (stg) * SS2;                                           \
    _Pragma("unroll")                                                             \
    for (int i_ = 0; i_ < 2; i_++) {                                              \
        int id_ = i_ * 256 + tid; int r_ = id_ >> 2, c_ = (id_ & 3) << 3;         \
        uint32_t so_ = us_ + (r_ * 40 + c_) * 2;                                  \
        size_t g_ = (size_t)(brow + r_) * lda + (k0) + c_;                        \
        cpa16(so_,        Ahi + g_);                                              \
        cpa16(so_ + ALO2, Alo + g_);                                              \
    }                                                                             \
    _Pragma("unroll")                                                             \
    for (int i_ = 0; i_ < BN / 64; i_++) {                                        \
        int id_ = i_ * 256 + tid; int r_ = id_ >> 2, c_ = (id_ & 3) << 3;         \
        uint32_t so_ = us_ + BHI2 + (r_ * 40 + c_) * 2;                           \
        size_t g_ = (size_t)(bcol + r_) * ldb + (k0) + c_;                        \
        cpa16(so_,        Bhi + g_);                                              \
        cpa16(so_ + BLOD, Blo + g_);                                              \
    }                                                                             \
} while (0)

    int fetch = 0;
    const int PRE = (2 < KT) ? 2 : KT;
    for (; fetch < PRE; fetch++) { ISSUE(fetch, fetch << 5); CP_COMMIT(); }

    for (int kt = 0; kt < KT; kt++) {
        CP_WAIT1();
        __syncthreads();
        if (fetch < KT) ISSUE(fetch % 3, fetch << 5);
        CP_COMMIT();
        fetch++;

        uint32_t us = ubase + (kt % 3) * SS2;
#pragma unroll
        for (int ks = 0; ks < 2; ks++) {
            uint32_t aH[2][4], aL[2][4], bH[NT][2], bL[NT][2];
#pragma unroll
            for (int mt = 0; mt < 2; mt++) {
                uint32_t ar = wm + mt * 16 + (lane & 15);
                uint32_t ac = ks * 16 + ((lane >> 4) << 3);
                uint32_t off = us + (ar * 40 + ac) * 2;
                ldsm4(aH[mt], off);
                ldsm4(aL[mt], off + ALO2);
            }
#pragma unroll
            for (int p = 0; p < NT / 2; p++) {
                uint32_t br = wn + p * 16 + ((lane >> 4) << 3) + (lane & 7);
                uint32_t bc = ks * 16 + (((lane >> 3) & 1) << 3);
                uint32_t off = us + BHI2 + (br * 40 + bc) * 2;
                uint32_t r[4];
                ldsm4(r, off);
                bH[p * 2][0] = r[0]; bH[p * 2][1] = r[1];
                bH[p * 2 + 1][0] = r[2]; bH[p * 2 + 1][1] = r[3];
                ldsm4(r, off + BLOD);
                bL[p * 2][0] = r[0]; bL[p * 2][1] = r[1];
                bL[p * 2 + 1][0] = r[2]; bL[p * 2 + 1][1] = r[3];
            }
#pragma unroll
            for (int mt = 0; mt < 2; mt++)
#pragma unroll
                for (int nt = 0; nt < NT; nt++) {
                    mma16816(acc[mt][nt], aH[mt], bH[nt]);   // hi*hi
                    mma16816(acc[mt][nt], aH[mt], bL[nt]);   // hi*lo
                    mma16816(acc[mt][nt], aL[mt], bH[nt]);   // lo*hi
                }
        }
    }
#undef ISSUE

    // epilogue
#pragma unroll
    for (int mt = 0; mt < 2; mt++) {
#pragma unroll
        for (int nt = 0; nt < NT; nt++) {
            int r0 = brow + wm + mt * 16 + (lane >> 2);
            int c0 = bcol + wn + nt * 8 + ((lane & 3) << 1);
#pragma unroll
            for (int half = 0; half < 2; half++) {
                int row = r0 + half * 8;
                float v0 = acc[mt][nt][half * 2 + 0];
                float v1 = acc[mt][nt][half * 2 + 1];
                if (EPI == 0) {
                    if (bias) { v0 += bias[c0]; v1 += bias[c0 + 1]; }
                } else if (EPI == 1) {
                    v0 = fmaxf(v0 + bias[c0], 0.f);
                    v1 = fmaxf(v1 + bias[c0 + 1], 0.f);
                } else {
                    const float* qr = qrel + ((size_t)((b << 10) + row) * 16 + h) * 33;
                    int d0 = c0 - row;     d0 = d0 < -16 ? -16 : (d0 > 16 ? 16 : d0);
                    int d1 = c0 + 1 - row; d1 = d1 < -16 ? -16 : (d1 > 16 ? 16 : d1);
                    v0 = (v0 + qr[d0 + 16]) * scale;
                    v1 = (v1 + qr[d1 + 16]) * scale;
                }
                if (STORE != 1)
                    *(float2*)(C + (size_t)row * ldc + c0) = make_float2(v0, v1);
                if (STORE >= 1) {
                    bf16 h0, l0, h1, l1;
                    bsplit(v0, h0, l0); bsplit(v1, h1, l1);
                    *(uint32_t*)(Chi + (size_t)row * ldc + c0) = pk2(h0, h1);
                    *(uint32_t*)(Clo + (size_t)row * ldc + c0) = pk2(l0, l1);
                }
            }
        }
    }
}

// ---------------- W [K,N] fp32 -> Wt [N,K] bf16 hi/lo -------------------------
__global__ void convert_wt_kernel(const float* __restrict__ W, bf16* __restrict__ hi,
                                  bf16* __restrict__ lo, int K, int N)
{
    __shared__ float t[32][33];
    int n0 = blockIdx.x * 32, k0 = blockIdx.y * 32;
    int tx = threadIdx.x, ty = threadIdx.y;
    for (int i = ty; i < 32; i += 8)
        t[i][tx] = W[(size_t)(k0 + i) * N + n0 + tx];
    __syncthreads();
    for (int i = ty; i < 32; i += 8) {
        float x = t[tx][i];
        bf16 h, l; bsplit(x, h, l);
        size_t o = (size_t)(n0 + i) * K + k0 + tx;
        hi[o] = h; lo[o] = l;
    }
}

// ---------------- elementwise fp32 -> bf16 hi/lo ------------------------------
__global__ void split_kernel(const float* __restrict__ X, bf16* __restrict__ hi,
                             bf16* __restrict__ lo)
{
    size_t i = ((size_t)blockIdx.x * 256 + threadIdx.x) * 4;
    float4 v = *(const float4*)(X + i);
    bf16 h0, h1, h2, h3, l0, l1, l2, l3;
    bsplit(v.x, h0, l0); bsplit(v.y, h1, l1);
    bsplit(v.z, h2, l2); bsplit(v.w, h3, l3);
    *(uint2*)(hi + i) = make_uint2(pk2(h0, h1), pk2(h2, h3));
    *(uint2*)(lo + i) = make_uint2(pk2(l0, l1), pk2(l2, l3));
}

// ---------------- V: [b,l,h*64+d] -> Vt [bh][d][l] bf16 hi/lo -----------------
__global__ void transpose_split_v(const float* __restrict__ V, bf16* __restrict__ hi,
                                  bf16* __restrict__ lo)
{
    __shared__ float t[32][33];
    int bh = blockIdx.z; int b = bh >> 4, h = bh & 15;
    int l0 = blockIdx.x * 32, d0 = blockIdx.y * 32;
    for (int i = threadIdx.y; i < 32; i += 8)
        t[i][threadIdx.x] = V[(size_t)(b * LL + l0 + i) * DD + h * DKK + d0 + threadIdx.x];
    __syncthreads();
    for (int i = threadIdx.y; i < 32; i += 8) {
        float x = t[threadIdx.x][i];
        bf16 hh, ll; bsplit(x, hh, ll);
        size_t o = ((size_t)bh * DKK + d0 + i) * LL + l0 + threadIdx.x;
        hi[o] = hh; lo[o] = ll;
    }
}

// ---------------- qrel[b,l,h,r] = Qh[b,l,h,:] . rel_k[r,:] --------------------
__global__ void qrel_kernel(const bf16* __restrict__ Qh, const bf16* __restrict__ Ql,
                            const float* __restrict__ rel_k, float* __restrict__ qrel)
{
    __shared__ float rk[NREL * DKK];
    int t = threadIdx.x;
    for (int i = t; i < NREL * DKK; i += 256) rk[i] = rel_k[i];
    __syncthreads();
    int w = t >> 5, lane = t & 31;
    int item = blockIdx.x * 8 + w;
    int bl = item >> 4, h = item & 15;
    size_t i0 = (size_t)bl * DD + h * DKK + lane * 2;
    float q0 = __bfloat162float(Qh[i0]) + __bfloat162float(Ql[i0]);
    float q1 = __bfloat162float(Qh[i0 + 1]) + __bfloat162float(Ql[i0 + 1]);
    for (int r = 0; r < NREL; r++) {
        float v = q0 * rk[r * DKK + lane * 2] + q1 * rk[r * DKK + lane * 2 + 1];
        v += __shfl_xor_sync(0xffffffffu, v, 16);
        v += __shfl_xor_sync(0xffffffffu, v, 8);
        v += __shfl_xor_sync(0xffffffffu, v, 4);
        v += __shfl_xor_sync(0xffffffffu, v, 2);
        v += __shfl_xor_sync(0xffffffffu, v, 1);
        if (lane == 0) qrel[(size_t)item * NREL + r] = v;
    }
}

// ---------------- softmax -> split bf16 probs + 33-bin relative sums ----------
__global__ void softmax_kernel(const float* __restrict__ S, bf16* __restrict__ Ph,
                               bf16* __restrict__ Pl, float* __restrict__ arel)
{
    int q = blockIdx.x, bh = blockIdx.y;
    size_t roff = ((size_t)bh * LL + q) * LL;
    const float* row = S + roff;
    bf16* ph = Ph + roff;
    bf16* pl = Pl + roff;
    int t = threadIdx.x;
    __shared__ float red[256];
    __shared__ float bins[NREL];
    if (t < NREL) bins[t] = 0.f;
    float v[4];
    float m = -1e30f;
#pragma unroll
    for (int i = 0; i < 4; i++) { v[i] = row[t + 256 * i]; m = fmaxf(m, v[i]); }
    red[t] = m; __syncthreads();
    for (int s = 128; s > 0; s >>= 1) { if (t < s) red[t] = fmaxf(red[t], red[t + s]); __syncthreads(); }
    m = red[0];
    __syncthreads();
    float s = 0.f;
#pragma unroll
    for (int i = 0; i < 4; i++) { v[i] = __expf(v[i] - m); s += v[i]; }
    red[t] = s; __syncthreads();
    for (int st = 128; st > 0; st >>= 1) { if (t < st) red[t] += red[t + st]; __syncthreads(); }
    float inv = 1.f / red[0];
    float slo = 0.f, shi = 0.f;
#pragma unroll
    for (int i = 0; i < 4; i++) {
        int j = t + 256 * i;
        float p = v[i] * inv;
        bf16 hh, ll; bsplit(p, hh, ll);
        ph[j] = hh; pl[j] = ll;
        int dist = j - q;
        if (dist < -16)      slo += p;
        else if (dist > 16)  shi += p;
        else                 atomicAdd(&bins[dist + 16], p);
    }
#pragma unroll
    for (int o = 16; o > 0; o >>= 1) {
        slo += __shfl_xor_sync(0xffffffffu, slo, o);
        shi += __shfl_xor_sync(0xffffffffu, shi, o);
    }
    if ((t & 31) == 0) {
        if (slo != 0.f) atomicAdd(&bins[0], slo);
        if (shi != 0.f) atomicAdd(&bins[32], shi);
    }
    __syncthreads();
    if (t < NREL) arel[((size_t)bh * LL + q) * NREL + t] = bins[t];
}

// ---------------- AT = attnout + arel @ rel_v -> split bf16 -------------------
__global__ void addrel_kernel(const float* __restrict__ attnout, const float* __restrict__ arel,
                              const float* __restrict__ rel_v,
                              bf16* __restrict__ ATh, bf16* __restrict__ ATl)
{
    __shared__ float rv[NREL * DKK];
    int t = threadIdx.x;
    for (int i = t; i < NREL * DKK; i += 256) rv[i] = rel_v[i];
    __syncthreads();
    int bh = blockIdx.y; int b = bh >> 4, h = bh & 15;
    int q = blockIdx.x * 4 + t / 64;
    int dd = t % 64;
    const float* ar = arel + ((size_t)bh * LL + q) * NREL;
    float sum = 0.f;
#pragma unroll
    for (int r = 0; r < NREL; r++) sum = fmaf(ar[r], rv[r * DKK + dd], sum);
    size_t idx = (size_t)(b * LL + q) * DD + h * DKK + dd;
    float x = attnout[idx] + sum;
    bf16 hh, ll; bsplit(x, hh, ll);
    ATh[idx] = hh; ATl[idx] = ll;
}

// ---------------- residual add + layernorm (+ optional split out) -------------
__global__ void ln_kernel(const float* __restrict__ X, const float* __restrict__ R,
                          const float* __restrict__ g, const float* __restrict__ be,
                          float* __restrict__ out, bf16* __restrict__ oh, bf16* __restrict__ ol)
{
    int row = blockIdx.x, t = threadIdx.x;
    __shared__ float red[256];
    float v[4];
    float s1 = 0.f;
#pragma unroll
    for (int i = 0; i < 4; i++) {
        int c = t + 256 * i;
        v[i] = X[(size_t)row * DD + c] + R[(size_t)row * DD + c];
        s1 += v[i];
    }
    red[t] = s1; __syncthreads();
    for (int s = 128; s > 0; s >>= 1) { if (t < s) red[t] += red[t + s]; __syncthreads(); }
    float mu = red[0] * (1.f / 1024.f);
    __syncthreads();
    float s2 = 0.f;
#pragma unroll
    for (int i = 0; i < 4; i++) { float d = v[i] - mu; s2 += d * d; }
    red[t] = s2; __syncthreads();
    for (int s = 128; s > 0; s >>= 1) { if (t < s) red[t] += red[t + s]; __syncthreads(); }
    float rstd = rsqrtf(red[0] * (1.f / 1024.f) + 1e-6f);
#pragma unroll
    for (int i = 0; i < 4; i++) {
        int c = t + 256 * i;
        float y = (v[i] - mu) * rstd * g[c] + be[c];
        out[(size_t)row * DD + c] = y;
        if (oh) {
            bf16 hh, ll; bsplit(y, hh, ll);
            oh[(size_t)row * DD + c] = hh;
            ol[(size_t)row * DD + c] = ll;
        }
    }
}

// ---------------- launch ------------------------------------------------------
extern "C" void kernel_launch(void* const* d_in, const int* in_sizes, int n_in,
                              void* d_out, int out_size)
{
    const float* q    = (const float*)d_in[0];
    const float* k    = (const float*)d_in[1];
    const float* v    = (const float*)d_in[2];
    const float* wq   = (const float*)d_in[3];
    const float* bq   = (const float*)d_in[4];
    const float* wk   = (const float*)d_in[5];
    const float* bk   = (const float*)d_in[6];
    const float* wv   = (const float*)d_in[7];
    const float* bv   = (const float*)d_in[8];
    const float* wfc  = (const float*)d_in[9];
    const float* bfc  = (const float*)d_in[10];
    const float* w1   = (const float*)d_in[11];
    const float* b1   = (const float*)d_in[12];
    const float* w2   = (const float*)d_in[13];
    const float* b2   = (const float*)d_in[14];
    const float* ln_g = (const float*)d_in[15];
    const float* ln_b = (const float*)d_in[16];
    const float* rel_k= (const float*)d_in[17];
    const float* rel_v= (const float*)d_in[18];
    float* out = (float*)d_out;

    float *gV, *gqrel, *gS, *garel, *gattn, *gfc, *gx1, *gy;
    cudaGetSymbolAddress((void**)&gV, g_V);
    cudaGetSymbolAddress((void**)&gqrel, g_qrel);
    cudaGetSymbolAddress((void**)&gS, g_S);
    cudaGetSymbolAddress((void**)&garel, g_arel);
    cudaGetSymbolAddress((void**)&gattn, g_attnout);
    cudaGetSymbolAddress((void**)&gfc, g_fc);
    cudaGetSymbolAddress((void**)&gx1, g_x1);
    cudaGetSymbolAddress((void**)&gy, g_y);

    bf16 *wqt_h,*wqt_l,*wkt_h,*wkt_l,*wvt_h,*wvt_l,*wft_h,*wft_l,*w1t_h,*w1t_l,*w2t_h,*w2t_l;
    bf16 *qs_h,*qs_l,*ks_h,*ks_l,*vs_h,*vs_l,*Qs_h,*Qs_l,*Kb_h,*Kb_l,*Vt_h,*Vt_l;
    bf16 *P_h,*P_l,*AT_h,*AT_l,*x1s_h,*x1s_l,*hid_h,*hid_l;
    cudaGetSymbolAddress((void**)&wqt_h, g_wqt_h); cudaGetSymbolAddress((void**)&wqt_l, g_wqt_l);
    cudaGetSymbolAddress((void**)&wkt_h, g_wkt_h); cudaGetSymbolAddress((void**)&wkt_l, g_wkt_l);
    cudaGetSymbolAddress((void**)&wvt_h, g_wvt_h); cudaGetSymbolAddress((void**)&wvt_l, g_wvt_l);
    cudaGetSymbolAddress((void**)&wft_h, g_wft_h); cudaGetSymbolAddress((void**)&wft_l, g_wft_l);
    cudaGetSymbolAddress((void**)&w1t_h, g_w1t_h); cudaGetSymbolAddress((void**)&w1t_l, g_w1t_l);
    cudaGetSymbolAddress((void**)&w2t_h, g_w2t_h); cudaGetSymbolAddress((void**)&w2t_l, g_w2t_l);
    cudaGetSymbolAddress((void**)&qs_h, g_qs_h);   cudaGetSymbolAddress((void**)&qs_l, g_qs_l);
    cudaGetSymbolAddress((void**)&ks_h, g_ks_h);   cudaGetSymbolAddress((void**)&ks_l, g_ks_l);
    cudaGetSymbolAddress((void**)&vs_h, g_vs_h);   cudaGetSymbolAddress((void**)&vs_l, g_vs_l);
    cudaGetSymbolAddress((void**)&Qs_h, g_Qs_h);   cudaGetSymbolAddress((void**)&Qs_l, g_Qs_l);
    cudaGetSymbolAddress((void**)&Kb_h, g_Kb_h);   cudaGetSymbolAddress((void**)&Kb_l, g_Kb_l);
    cudaGetSymbolAddress((void**)&Vt_h, g_Vt_h);   cudaGetSymbolAddress((void**)&Vt_l, g_Vt_l);
    cudaGetSymbolAddress((void**)&P_h, g_P_h);     cudaGetSymbolAddress((void**)&P_l, g_P_l);
    cudaGetSymbolAddress((void**)&AT_h, g_AT_h);   cudaGetSymbolAddress((void**)&AT_l, g_AT_l);
    cudaGetSymbolAddress((void**)&x1s_h, g_x1s_h); cudaGetSymbolAddress((void**)&x1s_l, g_x1s_l);
    cudaGetSymbolAddress((void**)&hid_h, g_hid_h); cudaGetSymbolAddress((void**)&hid_l, g_hid_l);

    const long long LD = (long long)LL * DD;
    const long long L2 = (long long)LL * LL;
    const int SM128 = 3 * (10240 + 80 * 128) * 2;   // 122880 B
    const int SM64  = 3 * (10240 + 80 * 64) * 2;    //  92160 B
    cudaFuncSetAttribute(mma_gemm<128,0,0>, cudaFuncAttributeMaxDynamicSharedMemorySize, SM128);
    cudaFuncSetAttribute(mma_gemm<128,0,1>, cudaFuncAttributeMaxDynamicSharedMemorySize, SM128);
    cudaFuncSetAttribute(mma_gemm<128,1,1>, cudaFuncAttributeMaxDynamicSharedMemorySize, SM128);
    cudaFuncSetAttribute(mma_gemm<128,2,0>, cudaFuncAttributeMaxDynamicSharedMemorySize, SM128);
    cudaFuncSetAttribute(mma_gemm<64,0,0>,  cudaFuncAttributeMaxDynamicSharedMemorySize, SM64);

    // 0) operand prep: weight transpose+split, input split
    convert_wt_kernel<<<dim3(32,32),  dim3(32,8)>>>(wq,  wqt_h, wqt_l, DD, DD);
    convert_wt_kernel<<<dim3(32,32),  dim3(32,8)>>>(wk,  wkt_h, wkt_l, DD, DD);
    convert_wt_kernel<<<dim3(32,32),  dim3(32,8)>>>(wv,  wvt_h, wvt_l, DD, DD);
    convert_wt_kernel<<<dim3(32,32),  dim3(32,8)>>>(wfc, wft_h, wft_l, DD, DD);
    convert_wt_kernel<<<dim3(128,32), dim3(32,8)>>>(w1,  w1t_h, w1t_l, DD, DI);
    convert_wt_kernel<<<dim3(32,128), dim3(32,8)>>>(w2,  w2t_h, w2t_l, DI, DD);
    split_kernel<<<MTOK*DD/1024, 256>>>(q, qs_h, qs_l);
    split_kernel<<<MTOK*DD/1024, 256>>>(k, ks_h, ks_l);
    split_kernel<<<MTOK*DD/1024, 256>>>(v, vs_h, vs_l);

    // 1) projections: Q,K -> split outputs; V -> fp32 for transpose
    mma_gemm<128,0,1><<<dim3(8,64,1),256,SM128>>>(qs_h,qs_l, wqt_h,wqt_l, bq, nullptr, Qs_h,Qs_l,
        DD, DD,DD,DD, 0,0,0,0,0,0, nullptr, 1.f);
    mma_gemm<128,0,1><<<dim3(8,64,1),256,SM128>>>(ks_h,ks_l, wkt_h,wkt_l, bk, nullptr, Kb_h,Kb_l,
        DD, DD,DD,DD, 0,0,0,0,0,0, nullptr, 1.f);
    mma_gemm<128,0,0><<<dim3(8,64,1),256,SM128>>>(vs_h,vs_l, wvt_h,wvt_l, bv, gV, nullptr,nullptr,
        DD, DD,DD,DD, 0,0,0,0,0,0, nullptr, 1.f);

    // 2) V transpose+split, qrel
    transpose_split_v<<<dim3(32,2,BB*HH), dim3(32,8)>>>(gV, Vt_h, Vt_l);
    qrel_kernel<<<MTOK*HH/8, 256>>>(Qs_h, Qs_l, rel_k, gqrel);

    // 3) scores = (Qh Kh^T + qrel) / 8   (batched over bh, K=64)
    mma_gemm<128,2,0><<<dim3(8,8,BB*HH),256,SM128>>>(
        Qs_h,Qs_l, Kb_h,Kb_l, nullptr, gS, nullptr,nullptr,
        DKK, DD,DD,LL, LD,DKK, LD,DKK, 16LL*L2,L2, gqrel, 0.125f);

    // 4) softmax -> split probs + relative bins
    softmax_kernel<<<dim3(LL, BB*HH), 256>>>(gS, P_h, P_l, garel);

    // 5) attnout = attn @ Vh ; AT = attnout + arel @ rel_v (split)
    mma_gemm<64,0,0><<<dim3(1,8,BB*HH),256,SM64>>>(
        P_h,P_l, Vt_h,Vt_l, nullptr, gattn, nullptr,nullptr,
        LL, LL,LL,DD, 16LL*L2,L2, 16LL*(long long)DKK*LL,(long long)DKK*LL, LD,DKK, nullptr, 1.f);
    addrel_kernel<<<dim3(LL/4, BB*HH), 256>>>(gattn, garel, rel_v, AT_h, AT_l);

    // 6) fc + residual(q) + LN (-> fp32 + split)
    mma_gemm<128,0,0><<<dim3(8,64,1),256,SM128>>>(AT_h,AT_l, wft_h,wft_l, bfc, gfc, nullptr,nullptr,
        DD, DD,DD,DD, 0,0,0,0,0,0, nullptr, 1.f);
    ln_kernel<<<MTOK,256>>>(gfc, q, ln_g, ln_b, gx1, x1s_h, x1s_l);

    // 7) FFN + residual + LN -> out
    mma_gemm<128,1,1><<<dim3(32,64,1),256,SM128>>>(x1s_h,x1s_l, w1t_h,w1t_l, b1, nullptr, hid_h,hid_l,
        DD, DD,DD,DI, 0,0,0,0,0,0, nullptr, 1.f);
    mma_gemm<128,0,0><<<dim3(8,64,1),256,SM128>>>(hid_h,hid_l, w2t_h,w2t_l, b2, gy, nullptr,nullptr,
        DI, DI,DI,DD, 0,0,0,0,0,0, nullptr, 1.f);
    ln_kernel<<<MTOK,256>>>(gy, gx1, ln_g, ln_b, out, nullptr, nullptr);
}

// round 9
// speedup vs baseline: 3.6336x; 1.0761x over previous
#include <cuda_runtime.h>
#include <cuda_bf16.h>
#include <cstdint>

#define BB 8
#define LL 1024
#define DD 1024
#define HH 16
#define DKK 64
#define DI 4096
#define MTOK (BB*LL)
#define NREL 33

using bf16 = __nv_bfloat16;

// ---------------- scratch (device globals) -----------------------------------
__device__ float g_V[MTOK*DD];
__device__ float g_qrel[(size_t)MTOK*HH*NREL];
__device__ float g_S[(size_t)BB*HH*LL*LL];    // 512MB scores
__device__ float g_arel[(size_t)BB*HH*LL*NREL];
__device__ float g_attnout[MTOK*DD];
__device__ float g_fc[MTOK*DD];
__device__ float g_x1[MTOK*DD];
__device__ float g_y[MTOK*DD];

// bf16 split operand pairs
__device__ bf16 g_wqt_h[DD*DD],  g_wqt_l[DD*DD];
__device__ bf16 g_wkt_h[DD*DD],  g_wkt_l[DD*DD];
__device__ bf16 g_wvt_h[DD*DD],  g_wvt_l[DD*DD];
__device__ bf16 g_wft_h[DD*DD],  g_wft_l[DD*DD];
__device__ bf16 g_w1t_h[(size_t)DI*DD], g_w1t_l[(size_t)DI*DD];
__device__ bf16 g_w2t_h[(size_t)DD*DI], g_w2t_l[(size_t)DD*DI];
__device__ bf16 g_qs_h[MTOK*DD], g_qs_l[MTOK*DD];
__device__ bf16 g_ks_h[MTOK*DD], g_ks_l[MTOK*DD];
__device__ bf16 g_vs_h[MTOK*DD], g_vs_l[MTOK*DD];
__device__ bf16 g_Qs_h[MTOK*DD], g_Qs_l[MTOK*DD];
__device__ bf16 g_Kb_h[MTOK*DD], g_Kb_l[MTOK*DD];
__device__ bf16 g_Vt_h[BB*HH*DKK*LL], g_Vt_l[BB*HH*DKK*LL];
__device__ bf16 g_P_h[(size_t)BB*HH*LL*LL], g_P_l[(size_t)BB*HH*LL*LL];
__device__ bf16 g_AT_h[MTOK*DD], g_AT_l[MTOK*DD];
__device__ bf16 g_x1s_h[MTOK*DD], g_x1s_l[MTOK*DD];
__device__ bf16 g_hid_h[(size_t)MTOK*DI], g_hid_l[(size_t)MTOK*DI];

// ---------------- helpers -----------------------------------------------------
__device__ __forceinline__ uint32_t smem_u32(const void* p) {
    uint32_t a;
    asm("{ .reg .u64 t; cvta.to.shared.u64 t, %1; cvt.u32.u64 %0, t; }" : "=r"(a) : "l"(p));
    return a;
}
__device__ __forceinline__ uint32_t pk2(bf16 a, bf16 b) {
    __nv_bfloat162 t = __halves2bfloat162(a, b);
    return *reinterpret_cast<uint32_t*>(&t);
}
__device__ __forceinline__ void bsplit(float x, bf16& h, bf16& l) {
    h = __float2bfloat16(x);
    l = __float2bfloat16(x - __bfloat162float(h));
}
__device__ __forceinline__ void ldsm4(uint32_t* r, uint32_t addr) {
    asm volatile("ldmatrix.sync.aligned.m8n8.x4.shared.b16 {%0,%1,%2,%3}, [%4];"
                 : "=r"(r[0]), "=r"(r[1]), "=r"(r[2]), "=r"(r[3]) : "r"(addr));
}
__device__ __forceinline__ void mma16816(float* d, const uint32_t* a, const uint32_t* b) {
    asm volatile("mma.sync.aligned.m16n8k16.row.col.f32.bf16.bf16.f32 "
                 "{%0,%1,%2,%3}, {%4,%5,%6,%7}, {%8,%9}, {%0,%1,%2,%3};"
                 : "+f"(d[0]), "+f"(d[1]), "+f"(d[2]), "+f"(d[3])
                 : "r"(a[0]), "r"(a[1]), "r"(a[2]), "r"(a[3]), "r"(b[0]), "r"(b[1]));
}
__device__ __forceinline__ void cpa16(uint32_t s, const void* g) {
    asm volatile("cp.async.cg.shared.global [%0], [%1], 16;" :: "r"(s), "l"(g));
}
#define CP_COMMIT() asm volatile("cp.async.commit_group;" ::: "memory")
#define CP_WAIT1()  asm volatile("cp.async.wait_group 1;" ::: "memory")

// ======== BIG-TILE GEMM: block 256x128, warp 64x64, 3-stage cp.async ==========
// C[row,col] = sum_k (Ahi+Alo)[row,k] * (Bhi+Blo)[col,k]  (3-term: hh+hl+lh)
// EPI: 0 = (+bias), 1 = (+bias, relu), 2 = (acc + qrel[clip]) * scale
// STORE: 0 = fp32 C, 1 = split Chi/Clo
template<int EPI, int STORE>
__global__ void __launch_bounds__(256, 1) mma_gemm2(
    const bf16* __restrict__ Ahi, const bf16* __restrict__ Alo,
    const bf16* __restrict__ Bhi, const bf16* __restrict__ Blo,
    const float* __restrict__ bias, float* __restrict__ C,
    bf16* __restrict__ Chi, bf16* __restrict__ Clo,
    int K, int lda, int ldb, int ldc,
    long long sAb, long long sAh, long long sBb, long long sBh,
    long long sCb, long long sCh,
    const float* __restrict__ qrel, float scale)
{
    constexpr int ALO = 20480;   // byte offsets inside a stage
    constexpr int BHI = 40960;
    constexpr int BLO = 51200;
    constexpr int SS  = 61440;   // stage size

    extern __shared__ __align__(16) char dsm[];
    uint32_t ubase = smem_u32(dsm);

    int z = blockIdx.z, b = z >> 4, h = z & 15;
    Ahi += (size_t)b * sAb + (size_t)h * sAh;
    Alo += (size_t)b * sAb + (size_t)h * sAh;
    Bhi += (size_t)b * sBb + (size_t)h * sBh;
    Blo += (size_t)b * sBb + (size_t)h * sBh;
    size_t coff = (size_t)b * sCb + (size_t)h * sCh;
    if (STORE == 0) C += coff;
    else { Chi += coff; Clo += coff; }

    int tid = threadIdx.x, wid = tid >> 5, lane = tid & 31;
    int brow = blockIdx.y * 256;
    int bcol = blockIdx.x * 128;
    int wm = (wid & 3) * 64;
    int wn = (wid >> 2) * 64;

    float acc[4][8][4];
#pragma unroll
    for (int mt = 0; mt < 4; mt++)
#pragma unroll
        for (int nt = 0; nt < 8; nt++)
#pragma unroll
            for (int i = 0; i < 4; i++) acc[mt][nt][i] = 0.f;

    const int KT = K >> 5;

#define ISSUE(stg, k0) do {                                                       \
    uint32_t us_ = ubase + (stg) * SS;                                            \
    _Pragma("unroll")                                                             \
    for (int i_ = 0; i_ < 4; i_++) {                                              \
        int id_ = i_ * 256 + tid; int r_ = id_ >> 2, c_ = (id_ & 3) << 3;         \
        uint32_t so_ = us_ + r_ * 80 + c_ * 2;                                    \
        size_t g_ = (size_t)(brow + r_) * lda + (k0) + c_;                        \
        cpa16(so_,       Ahi + g_);                                               \
        cpa16(so_ + ALO, Alo + g_);                                               \
    }                                                                             \
    _Pragma("unroll")                                                             \
    for (int i_ = 0; i_ < 2; i_++) {                                              \
        int id_ = i_ * 256 + tid; int r_ = id_ >> 2, c_ = (id_ & 3) << 3;         \
        uint32_t so_ = us_ + BHI + r_ * 80 + c_ * 2;                              \
        size_t g_ = (size_t)(bcol + r_) * ldb + (k0) + c_;                        \
        cpa16(so_,             Bhi + g_);                                         \
        cpa16(so_ + (BLO-BHI), Blo + g_);                                         \
    }                                                                             \
} while (0)

    int fetch = 0;
    const int PRE = (2 < KT) ? 2 : KT;
    for (; fetch < PRE; fetch++) { ISSUE(fetch, fetch << 5); CP_COMMIT(); }

    for (int kt = 0; kt < KT; kt++) {
        CP_WAIT1();
        __syncthreads();
        if (fetch < KT) ISSUE(fetch % 3, fetch << 5);
        CP_COMMIT();
        fetch++;

        uint32_t us = ubase + (kt % 3) * SS;
#pragma unroll
        for (int ks = 0; ks < 2; ks++) {
            uint32_t aH[4][4], aL[4][4], bH[8][2], bL[8][2];
#pragma unroll
            for (int mt = 0; mt < 4; mt++) {
                uint32_t ar = wm + mt * 16 + (lane & 15);
                uint32_t ac = ks * 16 + ((lane >> 4) << 3);
                uint32_t off = us + ar * 80 + ac * 2;
                ldsm4(aH[mt], off);
                ldsm4(aL[mt], off + ALO);
            }
#pragma unroll
            for (int p = 0; p < 4; p++) {
                uint32_t br = wn + p * 16 + ((lane >> 4) << 3) + (lane & 7);
                uint32_t bc = ks * 16 + (((lane >> 3) & 1) << 3);
                uint32_t off = us + BHI + br * 80 + bc * 2;
                uint32_t r[4];
                ldsm4(r, off);
                bH[p * 2][0] = r[0]; bH[p * 2][1] = r[1];
                bH[p * 2 + 1][0] = r[2]; bH[p * 2 + 1][1] = r[3];
                ldsm4(r, off + (BLO - BHI));
                bL[p * 2][0] = r[0]; bL[p * 2][1] = r[1];
                bL[p * 2 + 1][0] = r[2]; bL[p * 2 + 1][1] = r[3];
            }
#pragma unroll
            for (int mt = 0; mt < 4; mt++)
#pragma unroll
                for (int nt = 0; nt < 8; nt++) {
                    mma16816(acc[mt][nt], aH[mt], bH[nt]);
                    mma16816(acc[mt][nt], aH[mt], bL[nt]);
                    mma16816(acc[mt][nt], aL[mt], bH[nt]);
                }
        }
    }
#undef ISSUE

    // epilogue
#pragma unroll
    for (int mt = 0; mt < 4; mt++) {
#pragma unroll
        for (int nt = 0; nt < 8; nt++) {
            int r0 = brow + wm + mt * 16 + (lane >> 2);
            int c0 = bcol + wn + nt * 8 + ((lane & 3) << 1);
#pragma unroll
            for (int half = 0; half < 2; half++) {
                int row = r0 + half * 8;
                float v0 = acc[mt][nt][half * 2 + 0];
                float v1 = acc[mt][nt][half * 2 + 1];
                if (EPI == 0) {
                    if (bias) { v0 += bias[c0]; v1 += bias[c0 + 1]; }
                } else if (EPI == 1) {
                    v0 = fmaxf(v0 + bias[c0], 0.f);
                    v1 = fmaxf(v1 + bias[c0 + 1], 0.f);
                } else {
                    const float* qr = qrel + ((size_t)((b << 10) + row) * 16 + h) * 33;
                    int d0 = c0 - row;     d0 = d0 < -16 ? -16 : (d0 > 16 ? 16 : d0);
                    int d1 = c0 + 1 - row; d1 = d1 < -16 ? -16 : (d1 > 16 ? 16 : d1);
                    v0 = (v0 + qr[d0 + 16]) * scale;
                    v1 = (v1 + qr[d1 + 16]) * scale;
                }
                if (STORE == 0) {
                    *(float2*)(C + (size_t)row * ldc + c0) = make_float2(v0, v1);
                } else {
                    bf16 h0, l0, h1, l1;
                    bsplit(v0, h0, l0); bsplit(v1, h1, l1);
                    *(uint32_t*)(Chi + (size_t)row * ldc + c0) = pk2(h0, h1);
                    *(uint32_t*)(Clo + (size_t)row * ldc + c0) = pk2(l0, l1);
                }
            }
        }
    }
}

// ======== small-N GEMM (attn @ V), block 128x64, warp 32x32 ===================
template<int BN, int EPI, int STORE>
__global__ void __launch_bounds__(256, 1) mma_gemm(
    const bf16* __restrict__ Ahi, const bf16* __restrict__ Alo,
    const bf16* __restrict__ Bhi, const bf16* __restrict__ Blo,
    const float* __restrict__ bias, float* __restrict__ C,
    bf16* __restrict__ Chi, bf16* __restrict__ Clo,
    int K, int lda, int ldb, int ldc,
    long long sAb, long long sAh, long long sBb, long long sBh,
    long long sCb, long long sCh,
    const float* __restrict__ qrel, float scale)
{
    constexpr int NT = BN / 16;
    constexpr int SSH = 10240 + 80 * BN;
    constexpr int SS2 = SSH * 2;
    constexpr int ALO2 = 10240;
    constexpr int BHI2 = 20480;
    constexpr int BLOD = BN * 80;

    extern __shared__ __align__(16) char dsm[];
    uint32_t ubase = smem_u32(dsm);

    int z = blockIdx.z, b = z >> 4, h = z & 15;
    Ahi += (size_t)b * sAb + (size_t)h * sAh;
    Alo += (size_t)b * sAb + (size_t)h * sAh;
    Bhi += (size_t)b * sBb + (size_t)h * sBh;
    Blo += (size_t)b * sBb + (size_t)h * sBh;
    size_t coff = (size_t)b * sCb + (size_t)h * sCh;
    if (STORE != 1) C += coff;
    if (STORE >= 1) { Chi += coff; Clo += coff; }

    int tid = threadIdx.x, wid = tid >> 5, lane = tid & 31;
    int brow = blockIdx.y * 128;
    int bcol = blockIdx.x * BN;
    int wm = (wid & 3) * 32;
    int wn = (wid >> 2) * (BN / 2);

    float acc[2][NT][4];
#pragma unroll
    for (int mt = 0; mt < 2; mt++)
#pragma unroll
        for (int nt = 0; nt < NT; nt++)
#pragma unroll
            for (int i = 0; i < 4; i++) acc[mt][nt][i] = 0.f;

    const int KT = K >> 5;

#define ISSUE(stg, k0) do {                                                       \
    uint32_t us_ = ubase + (stg) * SS2;                                           \
    _Pragma("unroll")                                                             \
    for (int i_ = 0; i_ < 2; i_++) {                                              \
        int id_ = i_ * 256 + tid; int r_ = id_ >> 2, c_ = (id_ & 3) << 3;         \
        uint32_t so_ = us_ + (r_ * 40 + c_) * 2;                                  \
        size_t g_ = (size_t)(brow + r_) * lda + (k0) + c_;                        \
        cpa16(so_,        Ahi + g_);                                              \
        cpa16(so_ + ALO2, Alo + g_);                                              \
    }                                                                             \
    _Pragma("unroll")                                                             \
    for (int i_ = 0; i_ < BN / 64; i_++) {                                        \
        int id_ = i_ * 256 + tid; int r_ = id_ >> 2, c_ = (id_ & 3) << 3;         \
        uint32_t so_ = us_ + BHI2 + (r_ * 40 + c_) * 2;                           \
        size_t g_ = (size_t)(bcol + r_) * ldb + (k0) + c_;                        \
        cpa16(so_,        Bhi + g_);                                              \
        cpa16(so_ + BLOD, Blo + g_);                                              \
    }                                                                             \
} while (0)

    int fetch = 0;
    const int PRE = (2 < KT) ? 2 : KT;
    for (; fetch < PRE; fetch++) { ISSUE(fetch, fetch << 5); CP_COMMIT(); }

    for (int kt = 0; kt < KT; kt++) {
        CP_WAIT1();
        __syncthreads();
        if (fetch < KT) ISSUE(fetch % 3, fetch << 5);
        CP_COMMIT();
        fetch++;

        uint32_t us = ubase + (kt % 3) * SS2;
#pragma unroll
        for (int ks = 0; ks < 2; ks++) {
            uint32_t aH[2][4], aL[2][4], bH[NT][2], bL[NT][2];
#pragma unroll
            for (int mt = 0; mt < 2; mt++) {
                uint32_t ar = wm + mt * 16 + (lane & 15);
                uint32_t ac = ks * 16 + ((lane >> 4) << 3);
                uint32_t off = us + (ar * 40 + ac) * 2;
                ldsm4(aH[mt], off);
                ldsm4(aL[mt], off + ALO2);
            }
#pragma unroll
            for (int p = 0; p < NT / 2; p++) {
                uint32_t br = wn + p * 16 + ((lane >> 4) << 3) + (lane & 7);
                uint32_t bc = ks * 16 + (((lane >> 3) & 1) << 3);
                uint32_t off = us + BHI2 + (br * 40 + bc) * 2;
                uint32_t r[4];
                ldsm4(r, off);
                bH[p * 2][0] = r[0]; bH[p * 2][1] = r[1];
                bH[p * 2 + 1][0] = r[2]; bH[p * 2 + 1][1] = r[3];
                ldsm4(r, off + BLOD);
                bL[p * 2][0] = r[0]; bL[p * 2][1] = r[1];
                bL[p * 2 + 1][0] = r[2]; bL[p * 2 + 1][1] = r[3];
            }
#pragma unroll
            for (int mt = 0; mt < 2; mt++)
#pragma unroll
                for (int nt = 0; nt < NT; nt++) {
                    mma16816(acc[mt][nt], aH[mt], bH[nt]);
                    mma16816(acc[mt][nt], aH[mt], bL[nt]);
                    mma16816(acc[mt][nt], aL[mt], bH[nt]);
                }
        }
    }
#undef ISSUE

#pragma unroll
    for (int mt = 0; mt < 2; mt++) {
#pragma unroll
        for (int nt = 0; nt < NT; nt++) {
            int r0 = brow + wm + mt * 16 + (lane >> 2);
            int c0 = bcol + wn + nt * 8 + ((lane & 3) << 1);
#pragma unroll
            for (int half = 0; half < 2; half++) {
                int row = r0 + half * 8;
                float v0 = acc[mt][nt][half * 2 + 0];
                float v1 = acc[mt][nt][half * 2 + 1];
                if (EPI == 0) {
                    if (bias) { v0 += bias[c0]; v1 += bias[c0 + 1]; }
                } else if (EPI == 1) {
                    v0 = fmaxf(v0 + bias[c0], 0.f);
                    v1 = fmaxf(v1 + bias[c0 + 1], 0.f);
                } else {
                    const float* qr = qrel + ((size_t)((b << 10) + row) * 16 + h) * 33;
                    int d0 = c0 - row;     d0 = d0 < -16 ? -16 : (d0 > 16 ? 16 : d0);
                    int d1 = c0 + 1 - row; d1 = d1 < -16 ? -16 : (d1 > 16 ? 16 : d1);
                    v0 = (v0 + qr[d0 + 16]) * scale;
                    v1 = (v1 + qr[d1 + 16]) * scale;
                }
                if (STORE != 1)
                    *(float2*)(C + (size_t)row * ldc + c0) = make_float2(v0, v1);
                if (STORE >= 1) {
                    bf16 h0, l0, h1, l1;
                    bsplit(v0, h0, l0); bsplit(v1, h1, l1);
                    *(uint32_t*)(Chi + (size_t)row * ldc + c0) = pk2(h0, h1);
                    *(uint32_t*)(Clo + (size_t)row * ldc + c0) = pk2(l0, l1);
                }
            }
        }
    }
}

// ---------------- W [K,N] fp32 -> Wt [N,K] bf16 hi/lo -------------------------
__global__ void convert_wt_kernel(const float* __restrict__ W, bf16* __restrict__ hi,
                                  bf16* __restrict__ lo, int K, int N)
{
    __shared__ float t[32][33];
    int n0 = blockIdx.x * 32, k0 = blockIdx.y * 32;
    int tx = threadIdx.x, ty = threadIdx.y;
    for (int i = ty; i < 32; i += 8)
        t[i][tx] = W[(size_t)(k0 + i) * N + n0 + tx];
    __syncthreads();
    for (int i = ty; i < 32; i += 8) {
        float x = t[tx][i];
        bf16 h, l; bsplit(x, h, l);
        size_t o = (size_t)(n0 + i) * K + k0 + tx;
        hi[o] = h; lo[o] = l;
    }
}

// ---------------- elementwise fp32 -> bf16 hi/lo ------------------------------
__global__ void split_kernel(const float* __restrict__ X, bf16* __restrict__ hi,
                             bf16* __restrict__ lo)
{
    size_t i = ((size_t)blockIdx.x * 256 + threadIdx.x) * 4;
    float4 v = *(const float4*)(X + i);
    bf16 h0, h1, h2, h3, l0, l1, l2, l3;
    bsplit(v.x, h0, l0); bsplit(v.y, h1, l1);
    bsplit(v.z, h2, l2); bsplit(v.w, h3, l3);
    *(uint2*)(hi + i) = make_uint2(pk2(h0, h1), pk2(h2, h3));
    *(uint2*)(lo + i) = make_uint2(pk2(l0, l1), pk2(l2, l3));
}

// ---------------- V: [b,l,h*64+d] -> Vt [bh][d][l] bf16 hi/lo -----------------
__global__ void transpose_split_v(const float* __restrict__ V, bf16* __restrict__ hi,
                                  bf16* __restrict__ lo)
{
    __shared__ float t[32][33];
    int bh = blockIdx.z; int b = bh >> 4, h = bh & 15;
    int l0 = blockIdx.x * 32, d0 = blockIdx.y * 32;
    for (int i = threadIdx.y; i < 32; i += 8)
        t[i][threadIdx.x] = V[(size_t)(b * LL + l0 + i) * DD + h * DKK + d0 + threadIdx.x];
    __syncthreads();
    for (int i = threadIdx.y; i < 32; i += 8) {
        float x = t[threadIdx.x][i];
        bf16 hh, ll; bsplit(x, hh, ll);
        size_t o = ((size_t)bh * DKK + d0 + i) * LL + l0 + threadIdx.x;
        hi[o] = hh; lo[o] = ll;
    }
}

// ---------------- qrel[b,l,h,r] = Qh[b,l,h,:] . rel_k[r,:] --------------------
__global__ void qrel_kernel(const bf16* __restrict__ Qh, const bf16* __restrict__ Ql,
                            const float* __restrict__ rel_k, float* __restrict__ qrel)
{
    __shared__ float rk[NREL * DKK];
    int t = threadIdx.x;
    for (int i = t; i < NREL * DKK; i += 256) rk[i] = rel_k[i];
    __syncthreads();
    int w = t >> 5, lane = t & 31;
    int item = blockIdx.x * 8 + w;
    int bl = item >> 4, h = item & 15;
    size_t i0 = (size_t)bl * DD + h * DKK + lane * 2;
    float q0 = __bfloat162float(Qh[i0]) + __bfloat162float(Ql[i0]);
    float q1 = __bfloat162float(Qh[i0 + 1]) + __bfloat162float(Ql[i0 + 1]);
    for (int r = 0; r < NREL; r++) {
        float v = q0 * rk[r * DKK + lane * 2] + q1 * rk[r * DKK + lane * 2 + 1];
        v += __shfl_xor_sync(0xffffffffu, v, 16);
        v += __shfl_xor_sync(0xffffffffu, v, 8);
        v += __shfl_xor_sync(0xffffffffu, v, 4);
        v += __shfl_xor_sync(0xffffffffu, v, 2);
        v += __shfl_xor_sync(0xffffffffu, v, 1);
        if (lane == 0) qrel[(size_t)item * NREL + r] = v;
    }
}

// ---------------- softmax -> split bf16 probs + 33-bin relative sums ----------
__global__ void softmax_kernel(const float* __restrict__ S, bf16* __restrict__ Ph,
                               bf16* __restrict__ Pl, float* __restrict__ arel)
{
    int q = blockIdx.x, bh = blockIdx.y;
    size_t roff = ((size_t)bh * LL + q) * LL;
    const float* row = S + roff;
    bf16* ph = Ph + roff;
    bf16* pl = Pl + roff;
    int t = threadIdx.x;
    __shared__ float red[256];
    __shared__ float bins[NREL];
    if (t < NREL) bins[t] = 0.f;
    float v[4];
    float m = -1e30f;
#pragma unroll
    for (int i = 0; i < 4; i++) { v[i] = row[t + 256 * i]; m = fmaxf(m, v[i]); }
    red[t] = m; __syncthreads();
    for (int s = 128; s > 0; s >>= 1) { if (t < s) red[t] = fmaxf(red[t], red[t + s]); __syncthreads(); }
    m = red[0];
    __syncthreads();
    float s = 0.f;
#pragma unroll
    for (int i = 0; i < 4; i++) { v[i] = __expf(v[i] - m); s += v[i]; }
    red[t] = s; __syncthreads();
    for (int st = 128; st > 0; st >>= 1) { if (t < st) red[t] += red[t + st]; __syncthreads(); }
    float inv = 1.f / red[0];
    float slo = 0.f, shi = 0.f;
#pragma unroll
    for (int i = 0; i < 4; i++) {
        int j = t + 256 * i;
        float p = v[i] * inv;
        bf16 hh, ll; bsplit(p, hh, ll);
        ph[j] = hh; pl[j] = ll;
        int dist = j - q;
        if (dist < -16)      slo += p;
        else if (dist > 16)  shi += p;
        else                 atomicAdd(&bins[dist + 16], p);
    }
#pragma unroll
    for (int o = 16; o > 0; o >>= 1) {
        slo += __shfl_xor_sync(0xffffffffu, slo, o);
        shi += __shfl_xor_sync(0xffffffffu, shi, o);
    }
    if ((t & 31) == 0) {
        if (slo != 0.f) atomicAdd(&bins[0], slo);
        if (shi != 0.f) atomicAdd(&bins[32], shi);
    }
    __syncthreads();
    if (t < NREL) arel[((size_t)bh * LL + q) * NREL + t] = bins[t];
}

// ---------------- AT = attnout + arel @ rel_v -> split bf16 -------------------
__global__ void addrel_kernel(const float* __restrict__ attnout, const float* __restrict__ arel,
                              const float* __restrict__ rel_v,
                              bf16* __restrict__ ATh, bf16* __restrict__ ATl)
{
    __shared__ float rv[NREL * DKK];
    int t = threadIdx.x;
    for (int i = t; i < NREL * DKK; i += 256) rv[i] = rel_v[i];
    __syncthreads();
    int bh = blockIdx.y; int b = bh >> 4, h = bh & 15;
    int q = blockIdx.x * 4 + t / 64;
    int dd = t % 64;
    const float* ar = arel + ((size_t)bh * LL + q) * NREL;
    float sum = 0.f;
#pragma unroll
    for (int r = 0; r < NREL; r++) sum = fmaf(ar[r], rv[r * DKK + dd], sum);
    size_t idx = (size_t)(b * LL + q) * DD + h * DKK + dd;
    float x = attnout[idx] + sum;
    bf16 hh, ll; bsplit(x, hh, ll);
    ATh[idx] = hh; ATl[idx] = ll;
}

// ---------------- residual add + layernorm (+ optional split out) -------------
__global__ void ln_kernel(const float* __restrict__ X, const float* __restrict__ R,
                          const float* __restrict__ g, const float* __restrict__ be,
                          float* __restrict__ out, bf16* __restrict__ oh, bf16* __restrict__ ol)
{
    int row = blockIdx.x, t = threadIdx.x;
    __shared__ float red[256];
    float v[4];
    float s1 = 0.f;
#pragma unroll
    for (int i = 0; i < 4; i++) {
        int c = t + 256 * i;
        v[i] = X[(size_t)row * DD + c] + R[(size_t)row * DD + c];
        s1 += v[i];
    }
    red[t] = s1; __syncthreads();
    for (int s = 128; s > 0; s >>= 1) { if (t < s) red[t] += red[t + s]; __syncthreads(); }
    float mu = red[0] * (1.f / 1024.f);
    __syncthreads();
    float s2 = 0.f;
#pragma unroll
    for (int i = 0; i < 4; i++) { float d = v[i] - mu; s2 += d * d; }
    red[t] = s2; __syncthreads();
    for (int s = 128; s > 0; s >>= 1) { if (t < s) red[t] += red[t + s]; __syncthreads(); }
    float rstd = rsqrtf(red[0] * (1.f / 1024.f) + 1e-6f);
#pragma unroll
    for (int i = 0; i < 4; i++) {
        int c = t + 256 * i;
        float y = (v[i] - mu) * rstd * g[c] + be[c];
        out[(size_t)row * DD + c] = y;
        if (oh) {
            bf16 hh, ll; bsplit(y, hh, ll);
            oh[(size_t)row * DD + c] = hh;
            ol[(size_t)row * DD + c] = ll;
        }
    }
}

// ---------------- launch ------------------------------------------------------
extern "C" void kernel_launch(void* const* d_in, const int* in_sizes, int n_in,
                              void* d_out, int out_size)
{
    const float* q    = (const float*)d_in[0];
    const float* k    = (const float*)d_in[1];
    const float* v    = (const float*)d_in[2];
    const float* wq   = (const float*)d_in[3];
    const float* bq   = (const float*)d_in[4];
    const float* wk   = (const float*)d_in[5];
    const float* bk   = (const float*)d_in[6];
    const float* wv   = (const float*)d_in[7];
    const float* bv   = (const float*)d_in[8];
    const float* wfc  = (const float*)d_in[9];
    const float* bfc  = (const float*)d_in[10];
    const float* w1   = (const float*)d_in[11];
    const float* b1   = (const float*)d_in[12];
    const float* w2   = (const float*)d_in[13];
    const float* b2   = (const float*)d_in[14];
    const float* ln_g = (const float*)d_in[15];
    const float* ln_b = (const float*)d_in[16];
    const float* rel_k= (const float*)d_in[17];
    const float* rel_v= (const float*)d_in[18];
    float* out = (float*)d_out;

    float *gV, *gqrel, *gS, *garel, *gattn, *gfc, *gx1, *gy;
    cudaGetSymbolAddress((void**)&gV, g_V);
    cudaGetSymbolAddress((void**)&gqrel, g_qrel);
    cudaGetSymbolAddress((void**)&gS, g_S);
    cudaGetSymbolAddress((void**)&garel, g_arel);
    cudaGetSymbolAddress((void**)&gattn, g_attnout);
    cudaGetSymbolAddress((void**)&gfc, g_fc);
    cudaGetSymbolAddress((void**)&gx1, g_x1);
    cudaGetSymbolAddress((void**)&gy, g_y);

    bf16 *wqt_h,*wqt_l,*wkt_h,*wkt_l,*wvt_h,*wvt_l,*wft_h,*wft_l,*w1t_h,*w1t_l,*w2t_h,*w2t_l;
    bf16 *qs_h,*qs_l,*ks_h,*ks_l,*vs_h,*vs_l,*Qs_h,*Qs_l,*Kb_h,*Kb_l,*Vt_h,*Vt_l;
    bf16 *P_h,*P_l,*AT_h,*AT_l,*x1s_h,*x1s_l,*hid_h,*hid_l;
    cudaGetSymbolAddress((void**)&wqt_h, g_wqt_h); cudaGetSymbolAddress((void**)&wqt_l, g_wqt_l);
    cudaGetSymbolAddress((void**)&wkt_h, g_wkt_h); cudaGetSymbolAddress((void**)&wkt_l, g_wkt_l);
    cudaGetSymbolAddress((void**)&wvt_h, g_wvt_h); cudaGetSymbolAddress((void**)&wvt_l, g_wvt_l);
    cudaGetSymbolAddress((void**)&wft_h, g_wft_h); cudaGetSymbolAddress((void**)&wft_l, g_wft_l);
    cudaGetSymbolAddress((void**)&w1t_h, g_w1t_h); cudaGetSymbolAddress((void**)&w1t_l, g_w1t_l);
    cudaGetSymbolAddress((void**)&w2t_h, g_w2t_h); cudaGetSymbolAddress((void**)&w2t_l, g_w2t_l);
    cudaGetSymbolAddress((void**)&qs_h, g_qs_h);   cudaGetSymbolAddress((void**)&qs_l, g_qs_l);
    cudaGetSymbolAddress((void**)&ks_h, g_ks_h);   cudaGetSymbolAddress((void**)&ks_l, g_ks_l);
    cudaGetSymbolAddress((void**)&vs_h, g_vs_h);   cudaGetSymbolAddress((void**)&vs_l, g_vs_l);
    cudaGetSymbolAddress((void**)&Qs_h, g_Qs_h);   cudaGetSymbolAddress((void**)&Qs_l, g_Qs_l);
    cudaGetSymbolAddress((void**)&Kb_h, g_Kb_h);   cudaGetSymbolAddress((void**)&Kb_l, g_Kb_l);
    cudaGetSymbolAddress((void**)&Vt_h, g_Vt_h);   cudaGetSymbolAddress((void**)&Vt_l, g_Vt_l);
    cudaGetSymbolAddress((void**)&P_h, g_P_h);     cudaGetSymbolAddress((void**)&P_l, g_P_l);
    cudaGetSymbolAddress((void**)&AT_h, g_AT_h);   cudaGetSymbolAddress((void**)&AT_l, g_AT_l);
    cudaGetSymbolAddress((void**)&x1s_h, g_x1s_h); cudaGetSymbolAddress((void**)&x1s_l, g_x1s_l);
    cudaGetSymbolAddress((void**)&hid_h, g_hid_h); cudaGetSymbolAddress((void**)&hid_l, g_hid_l);

    const long long LD = (long long)LL * DD;
    const long long L2 = (long long)LL * LL;
    const int SMBIG = 3 * 61440;                    // 184320 B
    const int SM64  = 3 * (10240 + 80 * 64) * 2;    //  92160 B
    cudaFuncSetAttribute(mma_gemm2<0,0>, cudaFuncAttributeMaxDynamicSharedMemorySize, SMBIG);
    cudaFuncSetAttribute(mma_gemm2<0,1>, cudaFuncAttributeMaxDynamicSharedMemorySize, SMBIG);
    cudaFuncSetAttribute(mma_gemm2<1,1>, cudaFuncAttributeMaxDynamicSharedMemorySize, SMBIG);
    cudaFuncSetAttribute(mma_gemm2<2,0>, cudaFuncAttributeMaxDynamicSharedMemorySize, SMBIG);
    cudaFuncSetAttribute(mma_gemm<64,0,0>, cudaFuncAttributeMaxDynamicSharedMemorySize, SM64);

    // 0) operand prep
    convert_wt_kernel<<<dim3(32,32),  dim3(32,8)>>>(wq,  wqt_h, wqt_l, DD, DD);
    convert_wt_kernel<<<dim3(32,32),  dim3(32,8)>>>(wk,  wkt_h, wkt_l, DD, DD);
    convert_wt_kernel<<<dim3(32,32),  dim3(32,8)>>>(wv,  wvt_h, wvt_l, DD, DD);
    convert_wt_kernel<<<dim3(32,32),  dim3(32,8)>>>(wfc, wft_h, wft_l, DD, DD);
    convert_wt_kernel<<<dim3(128,32), dim3(32,8)>>>(w1,  w1t_h, w1t_l, DD, DI);
    convert_wt_kernel<<<dim3(32,128), dim3(32,8)>>>(w2,  w2t_h, w2t_l, DI, DD);
    split_kernel<<<MTOK*DD/1024, 256>>>(q, qs_h, qs_l);
    split_kernel<<<MTOK*DD/1024, 256>>>(k, ks_h, ks_l);
    split_kernel<<<MTOK*DD/1024, 256>>>(v, vs_h, vs_l);

    // 1) projections
    mma_gemm2<0,1><<<dim3(8,32,1),256,SMBIG>>>(qs_h,qs_l, wqt_h,wqt_l, bq, nullptr, Qs_h,Qs_l,
        DD, DD,DD,DD, 0,0,0,0,0,0, nullptr, 1.f);
    mma_gemm2<0,1><<<dim3(8,32,1),256,SMBIG>>>(ks_h,ks_l, wkt_h,wkt_l, bk, nullptr, Kb_h,Kb_l,
        DD, DD,DD,DD, 0,0,0,0,0,0, nullptr, 1.f);
    mma_gemm2<0,0><<<dim3(8,32,1),256,SMBIG>>>(vs_h,vs_l, wvt_h,wvt_l, bv, gV, nullptr,nullptr,
        DD, DD,DD,DD, 0,0,0,0,0,0, nullptr, 1.f);

    // 2) V transpose+split, qrel
    transpose_split_v<<<dim3(32,2,BB*HH), dim3(32,8)>>>(gV, Vt_h, Vt_l);
    qrel_kernel<<<MTOK*HH/8, 256>>>(Qs_h, Qs_l, rel_k, gqrel);

    // 3) scores = (Qh Kh^T + qrel) / 8
    mma_gemm2<2,0><<<dim3(8,4,BB*HH),256,SMBIG>>>(
        Qs_h,Qs_l, Kb_h,Kb_l, nullptr, gS, nullptr,nullptr,
        DKK, DD,DD,LL, LD,DKK, LD,DKK, 16LL*L2,L2, gqrel, 0.125f);

    // 4) softmax -> split probs + relative bins
    softmax_kernel<<<dim3(LL, BB*HH), 256>>>(gS, P_h, P_l, garel);

    // 5) attnout = attn @ Vh ; AT = attnout + arel @ rel_v (split)
    mma_gemm<64,0,0><<<dim3(1,8,BB*HH),256,SM64>>>(
        P_h,P_l, Vt_h,Vt_l, nullptr, gattn, nullptr,nullptr,
        LL, LL,LL,DD, 16LL*L2,L2, 16LL*(long long)DKK*LL,(long long)DKK*LL, LD,DKK, nullptr, 1.f);
    addrel_kernel<<<dim3(LL/4, BB*HH), 256>>>(gattn, garel, rel_v, AT_h, AT_l);

    // 6) fc + residual(q) + LN
    mma_gemm2<0,0><<<dim3(8,32,1),256,SMBIG>>>(AT_h,AT_l, wft_h,wft_l, bfc, gfc, nullptr,nullptr,
        DD, DD,DD,DD, 0,0,0,0,0,0, nullptr, 1.f);
    ln_kernel<<<MTOK,256>>>(gfc, q, ln_g, ln_b, gx1, x1s_h, x1s_l);

    // 7) FFN + residual + LN -> out
    mma_gemm2<1,1><<<dim3(32,32,1),256,SMBIG>>>(x1s_h,x1s_l, w1t_h,w1t_l, b1, nullptr, hid_h,hid_l,
        DD, DD,DD,DI, 0,0,0,0,0,0, nullptr, 1.f);
    mma_gemm2<0,0><<<dim3(8,32,1),256,SMBIG>>>(hid_h,hid_l, w2t_h,w2t_l, b2, gy, nullptr,nullptr,
        DI, DI,DI,DD, 0,0,0,0,0,0, nullptr, 1.f);
    ln_kernel<<<MTOK,256>>>(gy, gx1, ln_g, ln_b, out, nullptr, nullptr);
}

// round 11
// speedup vs baseline: 4.3389x; 1.1941x over previous
#include <cuda_runtime.h>
#include <cuda_bf16.h>
#include <cstdint>

#define BB 8
#define LL 1024
#define DD 1024
#define HH 16
#define DKK 64
#define DI 4096
#define MTOK (BB*LL)
#define NREL 33

using bf16 = __nv_bfloat16;

// ---------------- scratch (device globals) -----------------------------------
__device__ float g_V[MTOK*DD];
__device__ float g_qrel[(size_t)MTOK*HH*NREL];
__device__ float g_fc[MTOK*DD];
__device__ float g_x1[MTOK*DD];
__device__ float g_y[MTOK*DD];

// bf16 split operand pairs
__device__ bf16 g_wqt_h[DD*DD],  g_wqt_l[DD*DD];
__device__ bf16 g_wkt_h[DD*DD],  g_wkt_l[DD*DD];
__device__ bf16 g_wvt_h[DD*DD],  g_wvt_l[DD*DD];
__device__ bf16 g_wft_h[DD*DD],  g_wft_l[DD*DD];
__device__ bf16 g_w1t_h[(size_t)DI*DD], g_w1t_l[(size_t)DI*DD];
__device__ bf16 g_w2t_h[(size_t)DD*DI], g_w2t_l[(size_t)DD*DI];
__device__ bf16 g_qs_h[MTOK*DD], g_qs_l[MTOK*DD];
__device__ bf16 g_ks_h[MTOK*DD], g_ks_l[MTOK*DD];
__device__ bf16 g_vs_h[MTOK*DD], g_vs_l[MTOK*DD];
__device__ bf16 g_Qs_h[MTOK*DD], g_Qs_l[MTOK*DD];
__device__ bf16 g_Kb_h[MTOK*DD], g_Kb_l[MTOK*DD];
__device__ bf16 g_Vt_h[BB*HH*DKK*LL], g_Vt_l[BB*HH*DKK*LL];
__device__ bf16 g_AT_h[MTOK*DD], g_AT_l[MTOK*DD];
__device__ bf16 g_x1s_h[MTOK*DD], g_x1s_l[MTOK*DD];
__device__ bf16 g_hid_h[(size_t)MTOK*DI], g_hid_l[(size_t)MTOK*DI];

// ---------------- helpers -----------------------------------------------------
__device__ __forceinline__ uint32_t smem_u32(const void* p) {
    uint32_t a;
    asm("{ .reg .u64 t; cvta.to.shared.u64 t, %1; cvt.u32.u64 %0, t; }" : "=r"(a) : "l"(p));
    return a;
}
__device__ __forceinline__ uint32_t pk2(bf16 a, bf16 b) {
    __nv_bfloat162 t = __halves2bfloat162(a, b);
    return *reinterpret_cast<uint32_t*>(&t);
}
__device__ __forceinline__ void bsplit(float x, bf16& h, bf16& l) {
    h = __float2bfloat16(x);
    l = __float2bfloat16(x - __bfloat162float(h));
}
__device__ __forceinline__ void ldsm4(uint32_t* r, uint32_t addr) {
    asm volatile("ldmatrix.sync.aligned.m8n8.x4.shared.b16 {%0,%1,%2,%3}, [%4];"
                 : "=r"(r[0]), "=r"(r[1]), "=r"(r[2]), "=r"(r[3]) : "r"(addr));
}
__device__ __forceinline__ void mma16816(float* d, const uint32_t* a, const uint32_t* b) {
    asm volatile("mma.sync.aligned.m16n8k16.row.col.f32.bf16.bf16.f32 "
                 "{%0,%1,%2,%3}, {%4,%5,%6,%7}, {%8,%9}, {%0,%1,%2,%3};"
                 : "+f"(d[0]), "+f"(d[1]), "+f"(d[2]), "+f"(d[3])
                 : "r"(a[0]), "r"(a[1]), "r"(a[2]), "r"(a[3]), "r"(b[0]), "r"(b[1]));
}
__device__ __forceinline__ void cpa16(uint32_t s, const void* g) {
    asm volatile("cp.async.cg.shared.global [%0], [%1], 16;" :: "r"(s), "l"(g));
}
#define CP_COMMIT() asm volatile("cp.async.commit_group;" ::: "memory")
#define CP_WAIT1()  asm volatile("cp.async.wait_group 1;" ::: "memory")
#define CP_WAIT0()  asm volatile("cp.async.wait_group 0;" ::: "memory")

// ======== BIG-TILE GEMM: block 256x128, warp 64x64, 3-stage cp.async ==========
// EPI: 0 = (+bias), 1 = (+bias, relu)   STORE: 0 = fp32 C, 1 = split Chi/Clo
template<int EPI, int STORE>
__global__ void __launch_bounds__(256, 1) mma_gemm2(
    const bf16* __restrict__ Ahi, const bf16* __restrict__ Alo,
    const bf16* __restrict__ Bhi, const bf16* __restrict__ Blo,
    const float* __restrict__ bias, float* __restrict__ C,
    bf16* __restrict__ Chi, bf16* __restrict__ Clo,
    int K, int lda, int ldb, int ldc)
{
    constexpr int ALO = 20480;
    constexpr int BHI = 40960;
    constexpr int BLO = 51200;
    constexpr int SS  = 61440;

    extern __shared__ __align__(16) char dsm[];
    uint32_t ubase = smem_u32(dsm);

    int tid = threadIdx.x, wid = tid >> 5, lane = tid & 31;
    int brow = blockIdx.y * 256;
    int bcol = blockIdx.x * 128;
    int wm = (wid & 3) * 64;
    int wn = (wid >> 2) * 64;

    float acc[4][8][4];
#pragma unroll
    for (int mt = 0; mt < 4; mt++)
#pragma unroll
        for (int nt = 0; nt < 8; nt++)
#pragma unroll
            for (int i = 0; i < 4; i++) acc[mt][nt][i] = 0.f;

    const int KT = K >> 5;

#define ISSUE(stg, k0) do {                                                       \
    uint32_t us_ = ubase + (stg) * SS;                                            \
    _Pragma("unroll")                                                             \
    for (int i_ = 0; i_ < 4; i_++) {                                              \
        int id_ = i_ * 256 + tid; int r_ = id_ >> 2, c_ = (id_ & 3) << 3;         \
        uint32_t so_ = us_ + r_ * 80 + c_ * 2;                                    \
        size_t g_ = (size_t)(brow + r_) * lda + (k0) + c_;                        \
        cpa16(so_,       Ahi + g_);                                               \
        cpa16(so_ + ALO, Alo + g_);                                               \
    }                                                                             \
    _Pragma("unroll")                                                             \
    for (int i_ = 0; i_ < 2; i_++) {                                              \
        int id_ = i_ * 256 + tid; int r_ = id_ >> 2, c_ = (id_ & 3) << 3;         \
        uint32_t so_ = us_ + BHI + r_ * 80 + c_ * 2;                              \
        size_t g_ = (size_t)(bcol + r_) * ldb + (k0) + c_;                        \
        cpa16(so_,             Bhi + g_);                                         \
        cpa16(so_ + (BLO-BHI), Blo + g_);                                         \
    }                                                                             \
} while (0)

    int fetch = 0;
    const int PRE = (2 < KT) ? 2 : KT;
    for (; fetch < PRE; fetch++) { ISSUE(fetch, fetch << 5); CP_COMMIT(); }

    for (int kt = 0; kt < KT; kt++) {
        CP_WAIT1();
        __syncthreads();
        if (fetch < KT) ISSUE(fetch % 3, fetch << 5);
        CP_COMMIT();
        fetch++;

        uint32_t us = ubase + (kt % 3) * SS;
#pragma unroll
        for (int ks = 0; ks < 2; ks++) {
            uint32_t aH[4][4], aL[4][4], bH[8][2], bL[8][2];
#pragma unroll
            for (int mt = 0; mt < 4; mt++) {
                uint32_t ar = wm + mt * 16 + (lane & 15);
                uint32_t ac = ks * 16 + ((lane >> 4) << 3);
                uint32_t off = us + ar * 80 + ac * 2;
                ldsm4(aH[mt], off);
                ldsm4(aL[mt], off + ALO);
            }
#pragma unroll
            for (int p = 0; p < 4; p++) {
                uint32_t br = wn + p * 16 + ((lane >> 4) << 3) + (lane & 7);
                uint32_t bc = ks * 16 + (((lane >> 3) & 1) << 3);
                uint32_t off = us + BHI + br * 80 + bc * 2;
                uint32_t r[4];
                ldsm4(r, off);
                bH[p * 2][0] = r[0]; bH[p * 2][1] = r[1];
                bH[p * 2 + 1][0] = r[2]; bH[p * 2 + 1][1] = r[3];
                ldsm4(r, off + (BLO - BHI));
                bL[p * 2][0] = r[0]; bL[p * 2][1] = r[1];
                bL[p * 2 + 1][0] = r[2]; bL[p * 2 + 1][1] = r[3];
            }
#pragma unroll
            for (int mt = 0; mt < 4; mt++)
#pragma unroll
                for (int nt = 0; nt < 8; nt++) {
                    mma16816(acc[mt][nt], aH[mt], bH[nt]);
                    mma16816(acc[mt][nt], aH[mt], bL[nt]);
                    mma16816(acc[mt][nt], aL[mt], bH[nt]);
                }
        }
    }
#undef ISSUE

#pragma unroll
    for (int mt = 0; mt < 4; mt++) {
#pragma unroll
        for (int nt = 0; nt < 8; nt++) {
            int r0 = brow + wm + mt * 16 + (lane >> 2);
            int c0 = bcol + wn + nt * 8 + ((lane & 3) << 1);
#pragma unroll
            for (int half = 0; half < 2; half++) {
                int row = r0 + half * 8;
                float v0 = acc[mt][nt][half * 2 + 0];
                float v1 = acc[mt][nt][half * 2 + 1];
                if (EPI == 0) {
                    if (bias) { v0 += bias[c0]; v1 += bias[c0 + 1]; }
                } else {
                    v0 = fmaxf(v0 + bias[c0], 0.f);
                    v1 = fmaxf(v1 + bias[c0 + 1], 0.f);
                }
                if (STORE == 0) {
                    *(float2*)(C + (size_t)row * ldc + c0) = make_float2(v0, v1);
                } else {
                    bf16 h0, l0, h1, l1;
                    bsplit(v0, h0, l0); bsplit(v1, h1, l1);
                    *(uint32_t*)(Chi + (size_t)row * ldc + c0) = pk2(h0, h1);
                    *(uint32_t*)(Clo + (size_t)row * ldc + c0) = pk2(l0, l1);
                }
            }
        }
    }
}

// ======== FUSED FLASH ATTENTION ==============================================
// One block = (q-tile of 128 rows, one bh). 8 warps x 16 rows.
// Computes AT = softmax((QK^T + qrel)/8) @ V  +  rel-position value term,
// written as split bf16. No S / P materialization.
__global__ void __launch_bounds__(256, 1) flash_kernel(
    const bf16* __restrict__ Qh_, const bf16* __restrict__ Ql_,
    const bf16* __restrict__ Kh_, const bf16* __restrict__ Kl_,
    const bf16* __restrict__ Vth, const bf16* __restrict__ Vtl,
    const float* __restrict__ qrel, const float* __restrict__ rel_v,
    bf16* __restrict__ ATh, bf16* __restrict__ ATl)
{
    constexpr int uQ = 0, uK = 36864, uV = 110592;
    constexpr int uQR = 180224, uBAND = 197632, uRV = 214528, uSTAT = 222976;
    extern __shared__ __align__(16) char dsm[];
    uint32_t ub = smem_u32(dsm);
    float* qrel_s = (float*)(dsm + uQR);    // [128][34]
    float* band_s = (float*)(dsm + uBAND);  // [128][33]
    float* relv_s = (float*)(dsm + uRV);    // [33][64]
    float* stat_s = (float*)(dsm + uSTAT);  // [128][2] : m, l

    int tid = threadIdx.x, wid = tid >> 5, lane = tid & 31;
    int qi = blockIdx.x, bh = blockIdx.y;
    int bB = bh >> 4, hh = bh & 15;

    size_t qkbase = (size_t)bB * (LL * DD) + hh * DKK;  // + row*1024 + c
    size_t vbase  = (size_t)bh * (DKK * LL);            // + d*1024 + l

#define FISSUE_KV(t, st) do {                                                  \
    _Pragma("unroll") for (int i_ = 0; i_ < 4; i_++) {                         \
        int id_ = i_ * 256 + tid; int r_ = id_ >> 3, c_ = id_ & 7;             \
        uint32_t so_ = ub + uK + (st) * 36864 + r_ * 144 + c_ * 16;            \
        size_t g_ = qkbase + (size_t)((t) * 128 + r_) * 1024 + c_ * 8;         \
        cpa16(so_, Kh_ + g_); cpa16(so_ + 18432, Kl_ + g_);                    \
    }                                                                          \
    _Pragma("unroll") for (int i_ = 0; i_ < 4; i_++) {                         \
        int id_ = i_ * 256 + tid; int r_ = id_ >> 4, c_ = id_ & 15;            \
        uint32_t so_ = ub + uV + (st) * 34816 + r_ * 272 + c_ * 16;            \
        size_t g_ = vbase + (size_t)r_ * 1024 + (t) * 128 + c_ * 8;            \
        cpa16(so_, Vth + g_); cpa16(so_ + 17408, Vtl + g_);                    \
    }                                                                          \
} while (0)

    // group0 = Q + K0 + V0 ; group1 = K1 + V1
#pragma unroll
    for (int i = 0; i < 4; i++) {
        int id = i * 256 + tid; int r = id >> 3, c = id & 7;
        uint32_t so = ub + uQ + r * 144 + c * 16;
        size_t g = qkbase + (size_t)(qi * 128 + r) * 1024 + c * 8;
        cpa16(so, Qh_ + g); cpa16(so + 18432, Ql_ + g);
    }
    FISSUE_KV(0, 0);
    CP_COMMIT();
    FISSUE_KV(1, 1);
    CP_COMMIT();

    // qrel rows, rel_v, band init (covered by the first __syncthreads)
    for (int idx = tid; idx < 128 * 33; idx += 256) {
        int r = idx / 33, j = idx - r * 33;
        qrel_s[r * 34 + j] = qrel[((size_t)(bB * 1024 + qi * 128 + r) * 16 + hh) * 33 + j];
        band_s[r * 33 + j] = -1e30f;
    }
    for (int idx = tid; idx < 33 * 64; idx += 256) relv_s[idx] = rel_v[idx];

    CP_WAIT1();
    __syncthreads();

    // Q fragments (held in registers for all 8 k-tiles)
    uint32_t qAh[4][4], qAl[4][4];
    {
        uint32_t ar = (wid << 4) + (lane & 15);
#pragma unroll
        for (int ks = 0; ks < 4; ks++) {
            uint32_t ac = ks * 16 + ((lane >> 4) << 3);
            uint32_t off = ub + uQ + ar * 144 + ac * 2;
            ldsm4(qAh[ks], off);
            ldsm4(qAl[ks], off + 18432);
        }
    }

    int lrow0 = (wid << 4) + (lane >> 2), lrow1 = lrow0 + 8;
    int rowg0 = qi * 128 + lrow0, rowg1 = rowg0 + 8;
    float qw0_0  = qrel_s[lrow0 * 34 + 0],  qw32_0 = qrel_s[lrow0 * 34 + 32];
    float qw0_1  = qrel_s[lrow1 * 34 + 0],  qw32_1 = qrel_s[lrow1 * 34 + 32];

    float m0 = -1e30f, m1 = -1e30f, l0 = 0.f, l1 = 0.f;
    float sL0 = 0.f, sL1 = 0.f, sR0 = 0.f, sR1 = 0.f;
    float accO[8][4];
#pragma unroll
    for (int nt = 0; nt < 8; nt++)
#pragma unroll
        for (int i = 0; i < 4; i++) accO[nt][i] = 0.f;

    for (int ki = 0; ki < 8; ki++) {
        int st = ki & 1;
        if (ki > 0) {
            if (ki == 7) CP_WAIT0(); else CP_WAIT1();
            __syncthreads();
        }

        // ---- S = Q K^T (3-term split bf16)
        float accS[16][4];
#pragma unroll
        for (int nt = 0; nt < 16; nt++)
#pragma unroll
            for (int i = 0; i < 4; i++) accS[nt][i] = 0.f;
#pragma unroll
        for (int ks = 0; ks < 4; ks++) {
#pragma unroll
            for (int p = 0; p < 8; p++) {
                uint32_t br = p * 16 + ((lane >> 4) << 3) + (lane & 7);
                uint32_t bc = ks * 16 + (((lane >> 3) & 1) << 3);
                uint32_t off = ub + uK + st * 36864 + br * 144 + bc * 2;
                uint32_t rh[4], rl[4];
                ldsm4(rh, off);
                ldsm4(rl, off + 18432);
                uint32_t b0h[2] = {rh[0], rh[1]}, b1h[2] = {rh[2], rh[3]};
                uint32_t b0l[2] = {rl[0], rl[1]}, b1l[2] = {rl[2], rl[3]};
                mma16816(accS[2*p],     qAh[ks], b0h);
                mma16816(accS[2*p],     qAh[ks], b0l);
                mma16816(accS[2*p],     qAl[ks], b0h);
                mma16816(accS[2*p + 1], qAh[ks], b1h);
                mma16816(accS[2*p + 1], qAh[ks], b1l);
                mma16816(accS[2*p + 1], qAl[ks], b1h);
            }
        }

        // ---- raw scores: add rel-pos bias, scale, record band, track max
        bool band_tile = (ki >= qi - 1) && (ki <= qi + 1);
        float tmax0 = -1e30f, tmax1 = -1e30f;
        if (!band_tile) {
            float qa0 = (ki < qi) ? qw0_0 : qw32_0;
            float qa1 = (ki < qi) ? qw0_1 : qw32_1;
#pragma unroll
            for (int nt = 0; nt < 16; nt++) {
                accS[nt][0] = (accS[nt][0] + qa0) * 0.125f;
                accS[nt][1] = (accS[nt][1] + qa0) * 0.125f;
                accS[nt][2] = (accS[nt][2] + qa1) * 0.125f;
                accS[nt][3] = (accS[nt][3] + qa1) * 0.125f;
                tmax0 = fmaxf(tmax0, fmaxf(accS[nt][0], accS[nt][1]));
                tmax1 = fmaxf(tmax1, fmaxf(accS[nt][2], accS[nt][3]));
            }
        } else {
#pragma unroll
            for (int nt = 0; nt < 16; nt++) {
#pragma unroll
                for (int e = 0; e < 4; e++) {
                    int colg = ki * 128 + nt * 8 + ((lane & 3) << 1) + (e & 1);
                    int rg   = (e < 2) ? rowg0 : rowg1;
                    int lr   = (e < 2) ? lrow0 : lrow1;
                    int d = colg - rg;
                    float qr;
                    if (d < -16)      qr = (e < 2) ? qw0_0  : qw0_1;
                    else if (d > 16)  qr = (e < 2) ? qw32_0 : qw32_1;
                    else              qr = qrel_s[lr * 34 + d + 16];
                    float s = (accS[nt][e] + qr) * 0.125f;
                    if (d >= -16 && d <= 16) band_s[lr * 33 + d + 16] = s;
                    accS[nt][e] = s;
                    if (e < 2) tmax0 = fmaxf(tmax0, s); else tmax1 = fmaxf(tmax1, s);
                }
            }
        }
        tmax0 = fmaxf(tmax0, __shfl_xor_sync(0xffffffffu, tmax0, 1));
        tmax0 = fmaxf(tmax0, __shfl_xor_sync(0xffffffffu, tmax0, 2));
        tmax1 = fmaxf(tmax1, __shfl_xor_sync(0xffffffffu, tmax1, 1));
        tmax1 = fmaxf(tmax1, __shfl_xor_sync(0xffffffffu, tmax1, 2));

        float mn0 = fmaxf(m0, tmax0), mn1 = fmaxf(m1, tmax1);
        float sc0 = __expf(m0 - mn0), sc1 = __expf(m1 - mn1);
        m0 = mn0; m1 = mn1;
        l0 *= sc0; sL0 *= sc0; sR0 *= sc0;
        l1 *= sc1; sL1 *= sc1; sR1 *= sc1;
#pragma unroll
        for (int nt = 0; nt < 8; nt++) {
            accO[nt][0] *= sc0; accO[nt][1] *= sc0;
            accO[nt][2] *= sc1; accO[nt][3] *= sc1;
        }

        // ---- exp + category sums
        float es0 = 0.f, es1 = 0.f, eL0 = 0.f, eL1 = 0.f, eR0 = 0.f, eR1 = 0.f;
        if (!band_tile) {
#pragma unroll
            for (int nt = 0; nt < 16; nt++) {
                float e0 = __expf(accS[nt][0] - m0); accS[nt][0] = e0;
                float e1 = __expf(accS[nt][1] - m0); accS[nt][1] = e1;
                float e2 = __expf(accS[nt][2] - m1); accS[nt][2] = e2;
                float e3 = __expf(accS[nt][3] - m1); accS[nt][3] = e3;
                es0 += e0 + e1; es1 += e2 + e3;
            }
            if (ki < qi) { eL0 = es0; eL1 = es1; }
            else         { eR0 = es0; eR1 = es1; }
        } else {
#pragma unroll
            for (int nt = 0; nt < 16; nt++) {
#pragma unroll
                for (int e = 0; e < 4; e++) {
                    int colg = ki * 128 + nt * 8 + ((lane & 3) << 1) + (e & 1);
                    int rg = (e < 2) ? rowg0 : rowg1;
                    int d = colg - rg;
                    float mm = (e < 2) ? m0 : m1;
                    float ev = __expf(accS[nt][e] - mm);
                    accS[nt][e] = ev;
                    if (e < 2) {
                        es0 += ev;
                        if (d < -16) eL0 += ev; else if (d > 16) eR0 += ev;
                    } else {
                        es1 += ev;
                        if (d < -16) eL1 += ev; else if (d > 16) eR1 += ev;
                    }
                }
            }
        }
#pragma unroll
        for (int o = 1; o <= 2; o <<= 1) {
            es0 += __shfl_xor_sync(0xffffffffu, es0, o);
            es1 += __shfl_xor_sync(0xffffffffu, es1, o);
            eL0 += __shfl_xor_sync(0xffffffffu, eL0, o);
            eL1 += __shfl_xor_sync(0xffffffffu, eL1, o);
            eR0 += __shfl_xor_sync(0xffffffffu, eR0, o);
            eR1 += __shfl_xor_sync(0xffffffffu, eR1, o);
        }
        l0 += es0; sL0 += eL0; sR0 += eR0;
        l1 += es1; sL1 += eL1; sR1 += eR1;

        // ---- pack P (split bf16) in A-fragment order
        uint32_t phi[16][2], plo[16][2];
#pragma unroll
        for (int nt = 0; nt < 16; nt++) {
            bf16 h0, lo0, h1, lo1;
            bsplit(accS[nt][0], h0, lo0); bsplit(accS[nt][1], h1, lo1);
            phi[nt][0] = pk2(h0, h1); plo[nt][0] = pk2(lo0, lo1);
            bsplit(accS[nt][2], h0, lo0); bsplit(accS[nt][3], h1, lo1);
            phi[nt][1] = pk2(h0, h1); plo[nt][1] = pk2(lo0, lo1);
        }

        // ---- O += P @ V  (3-term: Phi*Vhi + Phi*Vlo + Plo*Vhi)
#pragma unroll
        for (int ks2 = 0; ks2 < 8; ks2++) {
            uint32_t aH[4] = { phi[2*ks2][0], phi[2*ks2][1], phi[2*ks2+1][0], phi[2*ks2+1][1] };
            uint32_t aL[4] = { plo[2*ks2][0], plo[2*ks2][1], plo[2*ks2+1][0], plo[2*ks2+1][1] };
#pragma unroll
            for (int p = 0; p < 4; p++) {
                uint32_t br = p * 16 + ((lane >> 4) << 3) + (lane & 7);
                uint32_t bc = ks2 * 16 + (((lane >> 3) & 1) << 3);
                uint32_t off = ub + uV + st * 34816 + br * 272 + bc * 2;
                uint32_t rh[4], rl[4];
                ldsm4(rh, off);
                ldsm4(rl, off + 17408);
                uint32_t b0h[2] = {rh[0], rh[1]}, b1h[2] = {rh[2], rh[3]};
                uint32_t b0l[2] = {rl[0], rl[1]}, b1l[2] = {rl[2], rl[3]};
                mma16816(accO[2*p],     aH, b0h);
                mma16816(accO[2*p],     aH, b0l);
                mma16816(accO[2*p],     aL, b0h);
                mma16816(accO[2*p + 1], aH, b1h);
                mma16816(accO[2*p + 1], aH, b1l);
                mma16816(accO[2*p + 1], aL, b1h);
            }
        }

        __syncthreads();                      // everyone done reading stage st
        if (ki < 6) { FISSUE_KV(ki + 2, st); CP_COMMIT(); }
    }
#undef FISSUE_KV

    // ---- band scores -> probabilities (using final m, l)
    if ((lane & 3) == 0) {
        stat_s[lrow0 * 2] = m0; stat_s[lrow0 * 2 + 1] = l0;
        stat_s[lrow1 * 2] = m1; stat_s[lrow1 * 2 + 1] = l1;
    }
    __syncthreads();
    if (tid < 128) {
        float mm = stat_s[tid * 2], invl = 1.f / stat_s[tid * 2 + 1];
#pragma unroll
        for (int j = 0; j < 33; j++)
            band_s[tid * 33 + j] = __expf(band_s[tid * 33 + j] - mm) * invl;
    }
    __syncthreads();

    // ---- final: O/l + (sL/l)*rel_v[0] + (sR/l)*rel_v[32] + band @ rel_v
    float inv0 = 1.f / l0, inv1 = 1.f / l1;
    float pa0 = sL0 * inv0, pb0 = sR0 * inv0;
    float pa1 = sL1 * inv1, pb1 = sR1 * inv1;
#pragma unroll
    for (int nt = 0; nt < 8; nt++) {
        int c0 = nt * 8 + ((lane & 3) << 1);
        accO[nt][0] = accO[nt][0] * inv0 + pa0 * relv_s[c0]     + pb0 * relv_s[32*64 + c0];
        accO[nt][1] = accO[nt][1] * inv0 + pa0 * relv_s[c0 + 1] + pb0 * relv_s[32*64 + c0 + 1];
        accO[nt][2] = accO[nt][2] * inv1 + pa1 * relv_s[c0]     + pb1 * relv_s[32*64 + c0];
        accO[nt][3] = accO[nt][3] * inv1 + pa1 * relv_s[c0 + 1] + pb1 * relv_s[32*64 + c0 + 1];
    }
#pragma unroll
    for (int j = 0; j < 33; j++) {
        float bp0 = band_s[lrow0 * 33 + j];
        float bp1 = band_s[lrow1 * 33 + j];
        const float* rv = relv_s + j * 64;
#pragma unroll
        for (int nt = 0; nt < 8; nt++) {
            int c0 = nt * 8 + ((lane & 3) << 1);
            float r0 = rv[c0], r1 = rv[c0 + 1];
            accO[nt][0] += bp0 * r0; accO[nt][1] += bp0 * r1;
            accO[nt][2] += bp1 * r0; accO[nt][3] += bp1 * r1;
        }
    }

    size_t obase = (size_t)(bB * 1024 + qi * 128) * 1024 + hh * 64;
#pragma unroll
    for (int nt = 0; nt < 8; nt++) {
        int c0 = nt * 8 + ((lane & 3) << 1);
        bf16 h0, lo0, h1, lo1;
        bsplit(accO[nt][0], h0, lo0); bsplit(accO[nt][1], h1, lo1);
        *(uint32_t*)(ATh + obase + (size_t)lrow0 * 1024 + c0) = pk2(h0, h1);
        *(uint32_t*)(ATl + obase + (size_t)lrow0 * 1024 + c0) = pk2(lo0, lo1);
        bsplit(accO[nt][2], h0, lo0); bsplit(accO[nt][3], h1, lo1);
        *(uint32_t*)(ATh + obase + (size_t)lrow1 * 1024 + c0) = pk2(h0, h1);
        *(uint32_t*)(ATl + obase + (size_t)lrow1 * 1024 + c0) = pk2(lo0, lo1);
    }
}

// ---------------- W [K,N] fp32 -> Wt [N,K] bf16 hi/lo -------------------------
__global__ void convert_wt_kernel(const float* __restrict__ W, bf16* __restrict__ hi,
                                  bf16* __restrict__ lo, int K, int N)
{
    __shared__ float t[32][33];
    int n0 = blockIdx.x * 32, k0 = blockIdx.y * 32;
    int tx = threadIdx.x, ty = threadIdx.y;
    for (int i = ty; i < 32; i += 8)
        t[i][tx] = W[(size_t)(k0 + i) * N + n0 + tx];
    __syncthreads();
    for (int i = ty; i < 32; i += 8) {
        float x = t[tx][i];
        bf16 h, l; bsplit(x, h, l);
        size_t o = (size_t)(n0 + i) * K + k0 + tx;
        hi[o] = h; lo[o] = l;
    }
}

// ---------------- elementwise fp32 -> bf16 hi/lo ------------------------------
__global__ void split_kernel(const float* __restrict__ X, bf16* __restrict__ hi,
                             bf16* __restrict__ lo)
{
    size_t i = ((size_t)blockIdx.x * 256 + threadIdx.x) * 4;
    float4 v = *(const float4*)(X + i);
    bf16 h0, h1, h2, h3, l0, l1, l2, l3;
    bsplit(v.x, h0, l0); bsplit(v.y, h1, l1);
    bsplit(v.z, h2, l2); bsplit(v.w, h3, l3);
    *(uint2*)(hi + i) = make_uint2(pk2(h0, h1), pk2(h2, h3));
    *(uint2*)(lo + i) = make_uint2(pk2(l0, l1), pk2(l2, l3));
}

// ---------------- V: [b,l,h*64+d] -> Vt [bh][d][l] bf16 hi/lo -----------------
__global__ void transpose_split_v(const float* __restrict__ V, bf16* __restrict__ hi,
                                  bf16* __restrict__ lo)
{
    __shared__ float t[32][33];
    int bh = blockIdx.z; int b = bh >> 4, h = bh & 15;
    int l0 = blockIdx.x * 32, d0 = blockIdx.y * 32;
    for (int i = threadIdx.y; i < 32; i += 8)
        t[i][threadIdx.x] = V[(size_t)(b * LL + l0 + i) * DD + h * DKK + d0 + threadIdx.x];
    __syncthreads();
    for (int i = threadIdx.y; i < 32; i += 8) {
        float x = t[threadIdx.x][i];
        bf16 hh, ll; bsplit(x, hh, ll);
        size_t o = ((size_t)bh * DKK + d0 + i) * LL + l0 + threadIdx.x;
        hi[o] = hh; lo[o] = ll;
    }
}

// ---------------- qrel[b,l,h,r] = Qh[b,l,h,:] . rel_k[r,:] --------------------
__global__ void qrel_kernel(const bf16* __restrict__ Qh, const bf16* __restrict__ Ql,
                            const float* __restrict__ rel_k, float* __restrict__ qrel)
{
    __shared__ float rk[NREL * DKK];
    int t = threadIdx.x;
    for (int i = t; i < NREL * DKK; i += 256) rk[i] = rel_k[i];
    __syncthreads();
    int w = t >> 5, lane = t & 31;
    int item = blockIdx.x * 8 + w;
    int bl = item >> 4, h = item & 15;
    size_t i0 = (size_t)bl * DD + h * DKK + lane * 2;
    float q0 = __bfloat162float(Qh[i0]) + __bfloat162float(Ql[i0]);
    float q1 = __bfloat162float(Qh[i0 + 1]) + __bfloat162float(Ql[i0 + 1]);
    for (int r = 0; r < NREL; r++) {
        float v = q0 * rk[r * DKK + lane * 2] + q1 * rk[r * DKK + lane * 2 + 1];
        v += __shfl_xor_sync(0xffffffffu, v, 16);
        v += __shfl_xor_sync(0xffffffffu, v, 8);
        v += __shfl_xor_sync(0xffffffffu, v, 4);
        v += __shfl_xor_sync(0xffffffffu, v, 2);
        v += __shfl_xor_sync(0xffffffffu, v, 1);
        if (lane == 0) qrel[(size_t)item * NREL + r] = v;
    }
}

// ---------------- residual add + layernorm (+ optional split out) -------------
__global__ void ln_kernel(const float* __restrict__ X, const float* __restrict__ R,
                          const float* __restrict__ g, const float* __restrict__ be,
                          float* __restrict__ out, bf16* __restrict__ oh, bf16* __restrict__ ol)
{
    int row = blockIdx.x, t = threadIdx.x;
    __shared__ float red[256];
    float v[4];
    float s1 = 0.f;
#pragma unroll
    for (int i = 0; i < 4; i++) {
        int c = t + 256 * i;
        v[i] = X[(size_t)row * DD + c] + R[(size_t)row * DD + c];
        s1 += v[i];
    }
    red[t] = s1; __syncthreads();
    for (int s = 128; s > 0; s >>= 1) { if (t < s) red[t] += red[t + s]; __syncthreads(); }
    float mu = red[0] * (1.f / 1024.f);
    __syncthreads();
    float s2 = 0.f;
#pragma unroll
    for (int i = 0; i < 4; i++) { float d = v[i] - mu; s2 += d * d; }
    red[t] = s2; __syncthreads();
    for (int s = 128; s > 0; s >>= 1) { if (t < s) red[t] += red[t + s]; __syncthreads(); }
    float rstd = rsqrtf(red[0] * (1.f / 1024.f) + 1e-6f);
#pragma unroll
    for (int i = 0; i < 4; i++) {
        int c = t + 256 * i;
        float y = (v[i] - mu) * rstd * g[c] + be[c];
        out[(size_t)row * DD + c] = y;
        if (oh) {
            bf16 hh, ll; bsplit(y, hh, ll);
            oh[(size_t)row * DD + c] = hh;
            ol[(size_t)row * DD + c] = ll;
        }
    }
}

// ---------------- launch ------------------------------------------------------
extern "C" void kernel_launch(void* const* d_in, const int* in_sizes, int n_in,
                              void* d_out, int out_size)
{
    const float* q    = (const float*)d_in[0];
    const float* k    = (const float*)d_in[1];
    const float* v    = (const float*)d_in[2];
    const float* wq   = (const float*)d_in[3];
    const float* bq   = (const float*)d_in[4];
    const float* wk   = (const float*)d_in[5];
    const float* bk   = (const float*)d_in[6];
    const float* wv   = (const float*)d_in[7];
    const float* bv   = (const float*)d_in[8];
    const float* wfc  = (const float*)d_in[9];
    const float* bfc  = (const float*)d_in[10];
    const float* w1   = (const float*)d_in[11];
    const float* b1   = (const float*)d_in[12];
    const float* w2   = (const float*)d_in[13];
    const float* b2   = (const float*)d_in[14];
    const float* ln_g = (const float*)d_in[15];
    const float* ln_b = (const float*)d_in[16];
    const float* rel_k= (const float*)d_in[17];
    const float* rel_v= (const float*)d_in[18];
    float* out = (float*)d_out;

    float *gV, *gqrel, *gfc, *gx1, *gy;
    cudaGetSymbolAddress((void**)&gV, g_V);
    cudaGetSymbolAddress((void**)&gqrel, g_qrel);
    cudaGetSymbolAddress((void**)&gfc, g_fc);
    cudaGetSymbolAddress((void**)&gx1, g_x1);
    cudaGetSymbolAddress((void**)&gy, g_y);

    bf16 *wqt_h,*wqt_l,*wkt_h,*wkt_l,*wvt_h,*wvt_l,*wft_h,*wft_l,*w1t_h,*w1t_l,*w2t_h,*w2t_l;
    bf16 *qs_h,*qs_l,*ks_h,*ks_l,*vs_h,*vs_l,*Qs_h,*Qs_l,*Kb_h,*Kb_l,*Vt_h,*Vt_l;
    bf16 *AT_h,*AT_l,*x1s_h,*x1s_l,*hid_h,*hid_l;
    cudaGetSymbolAddress((void**)&wqt_h, g_wqt_h); cudaGetSymbolAddress((void**)&wqt_l, g_wqt_l);
    cudaGetSymbolAddress((void**)&wkt_h, g_wkt_h); cudaGetSymbolAddress((void**)&wkt_l, g_wkt_l);
    cudaGetSymbolAddress((void**)&wvt_h, g_wvt_h); cudaGetSymbolAddress((void**)&wvt_l, g_wvt_l);
    cudaGetSymbolAddress((void**)&wft_h, g_wft_h); cudaGetSymbolAddress((void**)&wft_l, g_wft_l);
    cudaGetSymbolAddress((void**)&w1t_h, g_w1t_h); cudaGetSymbolAddress((void**)&w1t_l, g_w1t_l);
    cudaGetSymbolAddress((void**)&w2t_h, g_w2t_h); cudaGetSymbolAddress((void**)&w2t_l, g_w2t_l);
    cudaGetSymbolAddress((void**)&qs_h, g_qs_h);   cudaGetSymbolAddress((void**)&qs_l, g_qs_l);
    cudaGetSymbolAddress((void**)&ks_h, g_ks_h);   cudaGetSymbolAddress((void**)&ks_l, g_ks_l);
    cudaGetSymbolAddress((void**)&vs_h, g_vs_h);   cudaGetSymbolAddress((void**)&vs_l, g_vs_l);
    cudaGetSymbolAddress((void**)&Qs_h, g_Qs_h);   cudaGetSymbolAddress((void**)&Qs_l, g_Qs_l);
    cudaGetSymbolAddress((void**)&Kb_h, g_Kb_h);   cudaGetSymbolAddress((void**)&Kb_l, g_Kb_l);
    cudaGetSymbolAddress((void**)&Vt_h, g_Vt_h);   cudaGetSymbolAddress((void**)&Vt_l, g_Vt_l);
    cudaGetSymbolAddress((void**)&AT_h, g_AT_h);   cudaGetSymbolAddress((void**)&AT_l, g_AT_l);
    cudaGetSymbolAddress((void**)&x1s_h, g_x1s_h); cudaGetSymbolAddress((void**)&x1s_l, g_x1s_l);
    cudaGetSymbolAddress((void**)&hid_h, g_hid_h); cudaGetSymbolAddress((void**)&hid_l, g_hid_l);

    const int SMBIG   = 3 * 61440;   // 184320 B
    const int SMFLASH = 224000;      // flash kernel smem
    cudaFuncSetAttribute(mma_gemm2<0,0>, cudaFuncAttributeMaxDynamicSharedMemorySize, SMBIG);
    cudaFuncSetAttribute(mma_gemm2<0,1>, cudaFuncAttributeMaxDynamicSharedMemorySize, SMBIG);
    cudaFuncSetAttribute(mma_gemm2<1,1>, cudaFuncAttributeMaxDynamicSharedMemorySize, SMBIG);
    cudaFuncSetAttribute(flash_kernel,   cudaFuncAttributeMaxDynamicSharedMemorySize, SMFLASH);

    // 0) operand prep
    convert_wt_kernel<<<dim3(32,32),  dim3(32,8)>>>(wq,  wqt_h, wqt_l, DD, DD);
    convert_wt_kernel<<<dim3(32,32),  dim3(32,8)>>>(wk,  wkt_h, wkt_l, DD, DD);
    convert_wt_kernel<<<dim3(32,32),  dim3(32,8)>>>(wv,  wvt_h, wvt_l, DD, DD);
    convert_wt_kernel<<<dim3(32,32),  dim3(32,8)>>>(wfc, wft_h, wft_l, DD, DD);
    convert_wt_kernel<<<dim3(128,32), dim3(32,8)>>>(w1,  w1t_h, w1t_l, DD, DI);
    convert_wt_kernel<<<dim3(32,128), dim3(32,8)>>>(w2,  w2t_h, w2t_l, DI, DD);
    split_kernel<<<MTOK*DD/1024, 256>>>(q, qs_h, qs_l);
    split_kernel<<<MTOK*DD/1024, 256>>>(k, ks_h, ks_l);
    split_kernel<<<MTOK*DD/1024, 256>>>(v, vs_h, vs_l);

    // 1) projections
    mma_gemm2<0,1><<<dim3(8,32,1),256,SMBIG>>>(qs_h,qs_l, wqt_h,wqt_l, bq, nullptr, Qs_h,Qs_l, DD, DD,DD,DD);
    mma_gemm2<0,1><<<dim3(8,32,1),256,SMBIG>>>(ks_h,ks_l, wkt_h,wkt_l, bk, nullptr, Kb_h,Kb_l, DD, DD,DD,DD);
    mma_gemm2<0,0><<<dim3(8,32,1),256,SMBIG>>>(vs_h,vs_l, wvt_h,wvt_l, bv, gV, nullptr,nullptr, DD, DD,DD,DD);

    // 2) V transpose+split, qrel
    transpose_split_v<<<dim3(32,2,BB*HH), dim3(32,8)>>>(gV, Vt_h, Vt_l);
    qrel_kernel<<<MTOK*HH/8, 256>>>(Qs_h, Qs_l, rel_k, gqrel);

    // 3) fused attention -> AT split bf16
    flash_kernel<<<dim3(8, BB*HH), 256, SMFLASH>>>(
        Qs_h, Qs_l, Kb_h, Kb_l, Vt_h, Vt_l, gqrel, rel_v, AT_h, AT_l);

    // 4) fc + residual(q) + LN
    mma_gemm2<0,0><<<dim3(8,32,1),256,SMBIG>>>(AT_h,AT_l, wft_h,wft_l, bfc, gfc, nullptr,nullptr, DD, DD,DD,DD);
    ln_kernel<<<MTOK,256>>>(gfc, q, ln_g, ln_b, gx1, x1s_h, x1s_l);

    // 5) FFN + residual + LN -> out
    mma_gemm2<1,1><<<dim3(32,32,1),256,SMBIG>>>(x1s_h,x1s_l, w1t_h,w1t_l, b1, nullptr, hid_h,hid_l, DD, DD,DD,DI);
    mma_gemm2<0,0><<<dim3(8,32,1),256,SMBIG>>>(hid_h,hid_l, w2t_h,w2t_l, b2, gy, nullptr,nullptr, DI, DI,DI,DD);
    ln_kernel<<<MTOK,256>>>(gy, gx1, ln_g, ln_b, out, nullptr, nullptr);
}

// round 12
// speedup vs baseline: 5.9981x; 1.3824x over previous
#include <cuda_runtime.h>
#include <cuda_fp16.h>
#include <cstdint>

#define BB 8
#define LL 1024
#define DD 1024
#define HH 16
#define DKK 64
#define DI 4096
#define MTOK (BB*LL)
#define NREL 33

using fp16 = __half;

// ---------------- scratch (device globals) -----------------------------------
__device__ float g_V[MTOK*DD];
__device__ float g_qrel[(size_t)MTOK*HH*NREL];
__device__ float g_fc[MTOK*DD];
__device__ float g_x1[MTOK*DD];
__device__ float g_y[MTOK*DD];

// fp16 operands: B-side = split hi/lo pairs, A-side = plain fp16
__device__ fp16 g_wqt_h[DD*DD],  g_wqt_l[DD*DD];
__device__ fp16 g_wkt_h[DD*DD],  g_wkt_l[DD*DD];
__device__ fp16 g_wvt_h[DD*DD],  g_wvt_l[DD*DD];
__device__ fp16 g_wft_h[DD*DD],  g_wft_l[DD*DD];
__device__ fp16 g_w1t_h[(size_t)DI*DD], g_w1t_l[(size_t)DI*DD];
__device__ fp16 g_w2t_h[(size_t)DD*DI], g_w2t_l[(size_t)DD*DI];
__device__ fp16 g_qs[MTOK*DD];                       // input q (plain)
__device__ fp16 g_ks[MTOK*DD];                       // input k (plain)
__device__ fp16 g_vs[MTOK*DD];                       // input v (plain)
__device__ fp16 g_Qs[MTOK*DD];                       // Q proj (plain)
__device__ fp16 g_Kb_h[MTOK*DD], g_Kb_l[MTOK*DD];    // K proj (split: B of scores)
__device__ fp16 g_Vt_h[BB*HH*DKK*LL], g_Vt_l[BB*HH*DKK*LL]; // V [bh][d][l] (split)
__device__ fp16 g_AT[MTOK*DD];                       // attn out (plain)
__device__ fp16 g_x1s[MTOK*DD];                      // LN1 out (plain)
__device__ fp16 g_hid[(size_t)MTOK*DI];              // FFN hidden (plain)

// ---------------- helpers -----------------------------------------------------
__device__ __forceinline__ uint32_t smem_u32(const void* p) {
    uint32_t a;
    asm("{ .reg .u64 t; cvta.to.shared.u64 t, %1; cvt.u32.u64 %0, t; }" : "=r"(a) : "l"(p));
    return a;
}
__device__ __forceinline__ uint32_t hpk2(fp16 a, fp16 b) {
    __half2 t = __halves2half2(a, b);
    return *reinterpret_cast<uint32_t*>(&t);
}
__device__ __forceinline__ void hsplit(float x, fp16& h, fp16& l) {
    h = __float2half_rn(x);
    l = __float2half_rn(x - __half2float(h));
}
__device__ __forceinline__ void ldsm4(uint32_t* r, uint32_t addr) {
    asm volatile("ldmatrix.sync.aligned.m8n8.x4.shared.b16 {%0,%1,%2,%3}, [%4];"
                 : "=r"(r[0]), "=r"(r[1]), "=r"(r[2]), "=r"(r[3]) : "r"(addr));
}
__device__ __forceinline__ void mmaf16(float* d, const uint32_t* a, const uint32_t* b) {
    asm volatile("mma.sync.aligned.m16n8k16.row.col.f32.f16.f16.f32 "
                 "{%0,%1,%2,%3}, {%4,%5,%6,%7}, {%8,%9}, {%0,%1,%2,%3};"
                 : "+f"(d[0]), "+f"(d[1]), "+f"(d[2]), "+f"(d[3])
                 : "r"(a[0]), "r"(a[1]), "r"(a[2]), "r"(a[3]), "r"(b[0]), "r"(b[1]));
}
__device__ __forceinline__ void cpa16(uint32_t s, const void* g) {
    asm volatile("cp.async.cg.shared.global [%0], [%1], 16;" :: "r"(s), "l"(g));
}
#define CP_COMMIT() asm volatile("cp.async.commit_group;" ::: "memory")
#define CP_WAIT1()  asm volatile("cp.async.wait_group 1;" ::: "memory")
#define CP_WAIT0()  asm volatile("cp.async.wait_group 0;" ::: "memory")

// ======== fp16 2-term GEMM: block 128x128, warp 64x32, 3-stage, 2 CTA/SM ======
// C[row,col] = sum_k A[row,k] * (Bhi+Blo)[col,k]
// EPI: 0 = +bias, 1 = +bias,relu
// STORE: 0 = fp32 C, 1 = plain fp16 Co, 2 = split fp16 C2h/C2l
template<int EPI, int STORE>
__global__ void __launch_bounds__(256, 2) hgemm(
    const fp16* __restrict__ A,
    const fp16* __restrict__ Bhi, const fp16* __restrict__ Blo,
    const float* __restrict__ bias, float* __restrict__ C,
    fp16* __restrict__ Co, fp16* __restrict__ C2h, fp16* __restrict__ C2l,
    int K, int lda, int ldb, int ldc)
{
    constexpr int SS = 30720;   // stage: A 10240 | Bhi 10240 | Blo 10240
    extern __shared__ __align__(16) char dsm[];
    uint32_t ub = smem_u32(dsm);

    int tid = threadIdx.x, wid = tid >> 5, lane = tid & 31;
    int brow = blockIdx.y * 128;
    int bcol = blockIdx.x * 128;
    int wm = (wid & 1) * 64;
    int wn = (wid >> 1) * 32;

    float acc[4][4][4];
#pragma unroll
    for (int mt = 0; mt < 4; mt++)
#pragma unroll
        for (int nt = 0; nt < 4; nt++)
#pragma unroll
            for (int i = 0; i < 4; i++) acc[mt][nt][i] = 0.f;

    const int KT = K >> 5;

#define ISSUE(stg, k0) do {                                                       \
    uint32_t us_ = ub + (stg) * SS;                                               \
    _Pragma("unroll")                                                             \
    for (int i_ = 0; i_ < 2; i_++) {                                              \
        int id_ = i_ * 256 + tid; int r_ = id_ >> 2, c_ = (id_ & 3) << 3;         \
        uint32_t so_ = us_ + r_ * 80 + c_ * 2;                                    \
        size_t g_ = (size_t)(brow + r_) * lda + (k0) + c_;                        \
        cpa16(so_, A + g_);                                                       \
    }                                                                             \
    _Pragma("unroll")                                                             \
    for (int i_ = 0; i_ < 2; i_++) {                                              \
        int id_ = i_ * 256 + tid; int r_ = id_ >> 2, c_ = (id_ & 3) << 3;         \
        uint32_t so_ = us_ + 10240 + r_ * 80 + c_ * 2;                            \
        size_t g_ = (size_t)(bcol + r_) * ldb + (k0) + c_;                        \
        cpa16(so_,         Bhi + g_);                                             \
        cpa16(so_ + 10240, Blo + g_);                                             \
    }                                                                             \
} while (0)

    int fetch = 0;
    const int PRE = (2 < KT) ? 2 : KT;
    for (; fetch < PRE; fetch++) { ISSUE(fetch, fetch << 5); CP_COMMIT(); }

    for (int kt = 0; kt < KT; kt++) {
        if (kt == KT - 1) CP_WAIT0(); else CP_WAIT1();
        __syncthreads();
        if (fetch < KT) { ISSUE(fetch % 3, fetch << 5); CP_COMMIT(); fetch++; }

        uint32_t us = ub + (kt % 3) * SS;
#pragma unroll
        for (int ks = 0; ks < 2; ks++) {
            uint32_t aH[4][4], bH[4][2], bL[4][2];
#pragma unroll
            for (int mt = 0; mt < 4; mt++) {
                uint32_t ar = wm + mt * 16 + (lane & 15);
                uint32_t ac = ks * 16 + ((lane >> 4) << 3);
                ldsm4(aH[mt], us + ar * 80 + ac * 2);
            }
#pragma unroll
            for (int p = 0; p < 2; p++) {
                uint32_t br = wn + p * 16 + ((lane >> 4) << 3) + (lane & 7);
                uint32_t bc = ks * 16 + (((lane >> 3) & 1) << 3);
                uint32_t off = us + 10240 + br * 80 + bc * 2;
                uint32_t r[4];
                ldsm4(r, off);
                bH[p * 2][0] = r[0]; bH[p * 2][1] = r[1];
                bH[p * 2 + 1][0] = r[2]; bH[p * 2 + 1][1] = r[3];
                ldsm4(r, off + 10240);
                bL[p * 2][0] = r[0]; bL[p * 2][1] = r[1];
                bL[p * 2 + 1][0] = r[2]; bL[p * 2 + 1][1] = r[3];
            }
#pragma unroll
            for (int mt = 0; mt < 4; mt++)
#pragma unroll
                for (int nt = 0; nt < 4; nt++) {
                    mmaf16(acc[mt][nt], aH[mt], bH[nt]);
                    mmaf16(acc[mt][nt], aH[mt], bL[nt]);
                }
        }
        __syncthreads();        // all warps done with buffer before next ISSUE reuses it
    }
#undef ISSUE

    // epilogue
#pragma unroll
    for (int mt = 0; mt < 4; mt++) {
#pragma unroll
        for (int nt = 0; nt < 4; nt++) {
            int r0 = brow + wm + mt * 16 + (lane >> 2);
            int c0 = bcol + wn + nt * 8 + ((lane & 3) << 1);
#pragma unroll
            for (int half = 0; half < 2; half++) {
                int row = r0 + half * 8;
                float v0 = acc[mt][nt][half * 2 + 0] + bias[c0];
                float v1 = acc[mt][nt][half * 2 + 1] + bias[c0 + 1];
                if (EPI == 1) { v0 = fmaxf(v0, 0.f); v1 = fmaxf(v1, 0.f); }
                if (STORE == 0) {
                    *(float2*)(C + (size_t)row * ldc + c0) = make_float2(v0, v1);
                } else if (STORE == 1) {
                    *(uint32_t*)(Co + (size_t)row * ldc + c0) =
                        hpk2(__float2half_rn(v0), __float2half_rn(v1));
                } else {
                    fp16 h0, l0, h1, l1;
                    hsplit(v0, h0, l0); hsplit(v1, h1, l1);
                    *(uint32_t*)(C2h + (size_t)row * ldc + c0) = hpk2(h0, h1);
                    *(uint32_t*)(C2l + (size_t)row * ldc + c0) = hpk2(l0, l1);
                }
            }
        }
    }
}

// ======== FUSED FLASH ATTENTION (fp16 2-term) ================================
__global__ void __launch_bounds__(256, 1) flash_kernel(
    const fp16* __restrict__ Qs_, const fp16* __restrict__ Kh_, const fp16* __restrict__ Kl_,
    const fp16* __restrict__ Vth, const fp16* __restrict__ Vtl,
    const float* __restrict__ qrel, const float* __restrict__ rel_v,
    fp16* __restrict__ AT)
{
    constexpr int uQ = 0, uK = 18432, uV = 92160;
    constexpr int uQR = 161792, uBAND = 179200, uRV = 196096, uSTAT = 204544;
    extern __shared__ __align__(16) char dsm[];
    uint32_t ub = smem_u32(dsm);
    float* qrel_s = (float*)(dsm + uQR);    // [128][34]
    float* band_s = (float*)(dsm + uBAND);  // [128][33]
    float* relv_s = (float*)(dsm + uRV);    // [33][64]
    float* stat_s = (float*)(dsm + uSTAT);  // [128][2]

    int tid = threadIdx.x, wid = tid >> 5, lane = tid & 31;
    int qi = blockIdx.x, bh = blockIdx.y;
    int bB = bh >> 4, hh = bh & 15;

    size_t qkbase = (size_t)bB * (LL * DD) + hh * DKK;
    size_t vbase  = (size_t)bh * (DKK * LL);

#define FISSUE_KV(t, st) do {                                                  \
    _Pragma("unroll") for (int i_ = 0; i_ < 4; i_++) {                         \
        int id_ = i_ * 256 + tid; int r_ = id_ >> 3, c_ = id_ & 7;             \
        uint32_t so_ = ub + uK + (st) * 36864 + r_ * 144 + c_ * 16;            \
        size_t g_ = qkbase + (size_t)((t) * 128 + r_) * 1024 + c_ * 8;         \
        cpa16(so_, Kh_ + g_); cpa16(so_ + 18432, Kl_ + g_);                    \
    }                                                                          \
    _Pragma("unroll") for (int i_ = 0; i_ < 4; i_++) {                         \
        int id_ = i_ * 256 + tid; int r_ = id_ >> 4, c_ = id_ & 15;            \
        uint32_t so_ = ub + uV + (st) * 34816 + r_ * 272 + c_ * 16;            \
        size_t g_ = vbase + (size_t)r_ * 1024 + (t) * 128 + c_ * 8;            \
        cpa16(so_, Vth + g_); cpa16(so_ + 17408, Vtl + g_);                    \
    }                                                                          \
} while (0)

#pragma unroll
    for (int i = 0; i < 4; i++) {
        int id = i * 256 + tid; int r = id >> 3, c = id & 7;
        cpa16(ub + uQ + r * 144 + c * 16, Qs_ + qkbase + (size_t)(qi * 128 + r) * 1024 + c * 8);
    }
    FISSUE_KV(0, 0);
    CP_COMMIT();
    FISSUE_KV(1, 1);
    CP_COMMIT();

    for (int idx = tid; idx < 128 * 33; idx += 256) {
        int r = idx / 33, j = idx - r * 33;
        qrel_s[r * 34 + j] = qrel[((size_t)(bB * 1024 + qi * 128 + r) * 16 + hh) * 33 + j];
        band_s[r * 33 + j] = -1e30f;
    }
    for (int idx = tid; idx < 33 * 64; idx += 256) relv_s[idx] = rel_v[idx];

    CP_WAIT1();
    __syncthreads();

    uint32_t qA[4][4];
    {
        uint32_t ar = (wid << 4) + (lane & 15);
#pragma unroll
        for (int ks = 0; ks < 4; ks++) {
            uint32_t ac = ks * 16 + ((lane >> 4) << 3);
            ldsm4(qA[ks], ub + uQ + ar * 144 + ac * 2);
        }
    }

    int lrow0 = (wid << 4) + (lane >> 2), lrow1 = lrow0 + 8;
    int rowg0 = qi * 128 + lrow0, rowg1 = rowg0 + 8;
    float qw0_0  = qrel_s[lrow0 * 34 + 0],  qw32_0 = qrel_s[lrow0 * 34 + 32];
    float qw0_1  = qrel_s[lrow1 * 34 + 0],  qw32_1 = qrel_s[lrow1 * 34 + 32];

    float m0 = -1e30f, m1 = -1e30f, l0 = 0.f, l1 = 0.f;
    float sL0 = 0.f, sL1 = 0.f, sR0 = 0.f, sR1 = 0.f;
    float accO[8][4];
#pragma unroll
    for (int nt = 0; nt < 8; nt++)
#pragma unroll
        for (int i = 0; i < 4; i++) accO[nt][i] = 0.f;

    for (int ki = 0; ki < 8; ki++) {
        int st = ki & 1;
        if (ki > 0) {
            if (ki == 7) CP_WAIT0(); else CP_WAIT1();
            __syncthreads();
        }

        // ---- S = Q (Kh + Kl)^T
        float accS[16][4];
#pragma unroll
        for (int nt = 0; nt < 16; nt++)
#pragma unroll
            for (int i = 0; i < 4; i++) accS[nt][i] = 0.f;
#pragma unroll
        for (int ks = 0; ks < 4; ks++) {
#pragma unroll
            for (int p = 0; p < 8; p++) {
                uint32_t br = p * 16 + ((lane >> 4) << 3) + (lane & 7);
                uint32_t bc = ks * 16 + (((lane >> 3) & 1) << 3);
                uint32_t off = ub + uK + st * 36864 + br * 144 + bc * 2;
                uint32_t rh[4], rl[4];
                ldsm4(rh, off);
                ldsm4(rl, off + 18432);
                uint32_t b0h[2] = {rh[0], rh[1]}, b1h[2] = {rh[2], rh[3]};
                uint32_t b0l[2] = {rl[0], rl[1]}, b1l[2] = {rl[2], rl[3]};
                mmaf16(accS[2*p],     qA[ks], b0h);
                mmaf16(accS[2*p],     qA[ks], b0l);
                mmaf16(accS[2*p + 1], qA[ks], b1h);
                mmaf16(accS[2*p + 1], qA[ks], b1l);
            }
        }

        bool band_tile = (ki >= qi - 1) && (ki <= qi + 1);
        float tmax0 = -1e30f, tmax1 = -1e30f;
        if (!band_tile) {
            float qa0 = (ki < qi) ? qw0_0 : qw32_0;
            float qa1 = (ki < qi) ? qw0_1 : qw32_1;
#pragma unroll
            for (int nt = 0; nt < 16; nt++) {
                accS[nt][0] = (accS[nt][0] + qa0) * 0.125f;
                accS[nt][1] = (accS[nt][1] + qa0) * 0.125f;
                accS[nt][2] = (accS[nt][2] + qa1) * 0.125f;
                accS[nt][3] = (accS[nt][3] + qa1) * 0.125f;
                tmax0 = fmaxf(tmax0, fmaxf(accS[nt][0], accS[nt][1]));
                tmax1 = fmaxf(tmax1, fmaxf(accS[nt][2], accS[nt][3]));
            }
        } else {
#pragma unroll
            for (int nt = 0; nt < 16; nt++) {
#pragma unroll
                for (int e = 0; e < 4; e++) {
                    int colg = ki * 128 + nt * 8 + ((lane & 3) << 1) + (e & 1);
                    int rg   = (e < 2) ? rowg0 : rowg1;
                    int lr   = (e < 2) ? lrow0 : lrow1;
                    int d = colg - rg;
                    float qr;
                    if (d < -16)      qr = (e < 2) ? qw0_0  : qw0_1;
                    else if (d > 16)  qr = (e < 2) ? qw32_0 : qw32_1;
                    else              qr = qrel_s[lr * 34 + d + 16];
                    float s = (accS[nt][e] + qr) * 0.125f;
                    if (d >= -16 && d <= 16) band_s[lr * 33 + d + 16] = s;
                    accS[nt][e] = s;
                    if (e < 2) tmax0 = fmaxf(tmax0, s); else tmax1 = fmaxf(tmax1, s);
                }
            }
        }
        tmax0 = fmaxf(tmax0, __shfl_xor_sync(0xffffffffu, tmax0, 1));
        tmax0 = fmaxf(tmax0, __shfl_xor_sync(0xffffffffu, tmax0, 2));
        tmax1 = fmaxf(tmax1, __shfl_xor_sync(0xffffffffu, tmax1, 1));
        tmax1 = fmaxf(tmax1, __shfl_xor_sync(0xffffffffu, tmax1, 2));

        float mn0 = fmaxf(m0, tmax0), mn1 = fmaxf(m1, tmax1);
        float sc0 = __expf(m0 - mn0), sc1 = __expf(m1 - mn1);
        m0 = mn0; m1 = mn1;
        l0 *= sc0; sL0 *= sc0; sR0 *= sc0;
        l1 *= sc1; sL1 *= sc1; sR1 *= sc1;
#pragma unroll
        for (int nt = 0; nt < 8; nt++) {
            accO[nt][0] *= sc0; accO[nt][1] *= sc0;
            accO[nt][2] *= sc1; accO[nt][3] *= sc1;
        }

        float es0 = 0.f, es1 = 0.f, eL0 = 0.f, eL1 = 0.f, eR0 = 0.f, eR1 = 0.f;
        if (!band_tile) {
#pragma unroll
            for (int nt = 0; nt < 16; nt++) {
                float e0 = __expf(accS[nt][0] - m0); accS[nt][0] = e0;
                float e1 = __expf(accS[nt][1] - m0); accS[nt][1] = e1;
                float e2 = __expf(accS[nt][2] - m1); accS[nt][2] = e2;
                float e3 = __expf(accS[nt][3] - m1); accS[nt][3] = e3;
                es0 += e0 + e1; es1 += e2 + e3;
            }
            if (ki < qi) { eL0 = es0; eL1 = es1; }
            else         { eR0 = es0; eR1 = es1; }
        } else {
#pragma unroll
            for (int nt = 0; nt < 16; nt++) {
#pragma unroll
                for (int e = 0; e < 4; e++) {
                    int colg = ki * 128 + nt * 8 + ((lane & 3) << 1) + (e & 1);
                    int rg = (e < 2) ? rowg0 : rowg1;
                    int d = colg - rg;
                    float mm = (e < 2) ? m0 : m1;
                    float ev = __expf(accS[nt][e] - mm);
                    accS[nt][e] = ev;
                    if (e < 2) {
                        es0 += ev;
                        if (d < -16) eL0 += ev; else if (d > 16) eR0 += ev;
                    } else {
                        es1 += ev;
                        if (d < -16) eL1 += ev; else if (d > 16) eR1 += ev;
                    }
                }
            }
        }
#pragma unroll
        for (int o = 1; o <= 2; o <<= 1) {
            es0 += __shfl_xor_sync(0xffffffffu, es0, o);
            es1 += __shfl_xor_sync(0xffffffffu, es1, o);
            eL0 += __shfl_xor_sync(0xffffffffu, eL0, o);
            eL1 += __shfl_xor_sync(0xffffffffu, eL1, o);
            eR0 += __shfl_xor_sync(0xffffffffu, eR0, o);
            eR1 += __shfl_xor_sync(0xffffffffu, eR1, o);
        }
        l0 += es0; sL0 += eL0; sR0 += eR0;
        l1 += es1; sL1 += eL1; sR1 += eR1;

        // ---- pack P as plain fp16 in A-fragment order
        uint32_t ph[16][2];
#pragma unroll
        for (int nt = 0; nt < 16; nt++) {
            ph[nt][0] = hpk2(__float2half_rn(accS[nt][0]), __float2half_rn(accS[nt][1]));
            ph[nt][1] = hpk2(__float2half_rn(accS[nt][2]), __float2half_rn(accS[nt][3]));
        }

        // ---- O += P (Vh + Vl)
#pragma unroll
        for (int ks2 = 0; ks2 < 8; ks2++) {
            uint32_t aH[4] = { ph[2*ks2][0], ph[2*ks2][1], ph[2*ks2+1][0], ph[2*ks2+1][1] };
#pragma unroll
            for (int p = 0; p < 4; p++) {
                uint32_t br = p * 16 + ((lane >> 4) << 3) + (lane & 7);
                uint32_t bc = ks2 * 16 + (((lane >> 3) & 1) << 3);
                uint32_t off = ub + uV + st * 34816 + br * 272 + bc * 2;
                uint32_t rh[4], rl[4];
                ldsm4(rh, off);
                ldsm4(rl, off + 17408);
                uint32_t b0h[2] = {rh[0], rh[1]}, b1h[2] = {rh[2], rh[3]};
                uint32_t b0l[2] = {rl[0], rl[1]}, b1l[2] = {rl[2], rl[3]};
                mmaf16(accO[2*p],     aH, b0h);
                mmaf16(accO[2*p],     aH, b0l);
                mmaf16(accO[2*p + 1], aH, b1h);
                mmaf16(accO[2*p + 1], aH, b1l);
            }
        }

        __syncthreads();
        if (ki < 6) { FISSUE_KV(ki + 2, st); CP_COMMIT(); }
    }
#undef FISSUE_KV

    if ((lane & 3) == 0) {
        stat_s[lrow0 * 2] = m0; stat_s[lrow0 * 2 + 1] = l0;
        stat_s[lrow1 * 2] = m1; stat_s[lrow1 * 2 + 1] = l1;
    }
    __syncthreads();
    if (tid < 128) {
        float mm = stat_s[tid * 2], invl = 1.f / stat_s[tid * 2 + 1];
#pragma unroll
        for (int j = 0; j < 33; j++)
            band_s[tid * 33 + j] = __expf(band_s[tid * 33 + j] - mm) * invl;
    }
    __syncthreads();

    float inv0 = 1.f / l0, inv1 = 1.f / l1;
    float pa0 = sL0 * inv0, pb0 = sR0 * inv0;
    float pa1 = sL1 * inv1, pb1 = sR1 * inv1;
#pragma unroll
    for (int nt = 0; nt < 8; nt++) {
        int c0 = nt * 8 + ((lane & 3) << 1);
        accO[nt][0] = accO[nt][0] * inv0 + pa0 * relv_s[c0]     + pb0 * relv_s[32*64 + c0];
        accO[nt][1] = accO[nt][1] * inv0 + pa0 * relv_s[c0 + 1] + pb0 * relv_s[32*64 + c0 + 1];
        accO[nt][2] = accO[nt][2] * inv1 + pa1 * relv_s[c0]     + pb1 * relv_s[32*64 + c0];
        accO[nt][3] = accO[nt][3] * inv1 + pa1 * relv_s[c0 + 1] + pb1 * relv_s[32*64 + c0 + 1];
    }
#pragma unroll
    for (int j = 0; j < 33; j++) {
        float bp0 = band_s[lrow0 * 33 + j];
        float bp1 = band_s[lrow1 * 33 + j];
        const float* rv = relv_s + j * 64;
#pragma unroll
        for (int nt = 0; nt < 8; nt++) {
            int c0 = nt * 8 + ((lane & 3) << 1);
            float r0 = rv[c0], r1 = rv[c0 + 1];
            accO[nt][0] += bp0 * r0; accO[nt][1] += bp0 * r1;
            accO[nt][2] += bp1 * r0; accO[nt][3] += bp1 * r1;
        }
    }

    size_t obase = (size_t)(bB * 1024 + qi * 128) * 1024 + hh * 64;
#pragma unroll
    for (int nt = 0; nt < 8; nt++) {
        int c0 = nt * 8 + ((lane & 3) << 1);
        *(uint32_t*)(AT + obase + (size_t)lrow0 * 1024 + c0) =
            hpk2(__float2half_rn(accO[nt][0]), __float2half_rn(accO[nt][1]));
        *(uint32_t*)(AT + obase + (size_t)lrow1 * 1024 + c0) =
            hpk2(__float2half_rn(accO[nt][2]), __float2half_rn(accO[nt][3]));
    }
}

// ---------------- W [K,N] fp32 -> Wt [N,K] fp16 hi/lo -------------------------
__global__ void convert_wt_kernel(const float* __restrict__ W, fp16* __restrict__ hi,
                                  fp16* __restrict__ lo, int K, int N)
{
    __shared__ float t[32][33];
    int n0 = blockIdx.x * 32, k0 = blockIdx.y * 32;
    int tx = threadIdx.x, ty = threadIdx.y;
    for (int i = ty; i < 32; i += 8)
        t[i][tx] = W[(size_t)(k0 + i) * N + n0 + tx];
    __syncthreads();
    for (int i = ty; i < 32; i += 8) {
        float x = t[tx][i];
        fp16 h, l; hsplit(x, h, l);
        size_t o = (size_t)(n0 + i) * K + k0 + tx;
        hi[o] = h; lo[o] = l;
    }
}

// ---------------- fused q/k/v fp32 -> plain fp16 ------------------------------
__global__ void split3_kernel(const float* __restrict__ q, const float* __restrict__ k,
                              const float* __restrict__ v,
                              fp16* __restrict__ qo, fp16* __restrict__ ko, fp16* __restrict__ vo)
{
    const float* X = (blockIdx.y == 0) ? q : (blockIdx.y == 1) ? k : v;
    fp16* O = (blockIdx.y == 0) ? qo : (blockIdx.y == 1) ? ko : vo;
    size_t i = ((size_t)blockIdx.x * 256 + threadIdx.x) * 4;
    float4 w = *(const float4*)(X + i);
    *(uint2*)(O + i) = make_uint2(hpk2(__float2half_rn(w.x), __float2half_rn(w.y)),
                                  hpk2(__float2half_rn(w.z), __float2half_rn(w.w)));
}

// ---------------- V: [b,l,h*64+d] -> Vt [bh][d][l] fp16 hi/lo -----------------
__global__ void transpose_split_v(const float* __restrict__ V, fp16* __restrict__ hi,
                                  fp16* __restrict__ lo)
{
    __shared__ float t[32][33];
    int bh = blockIdx.z; int b = bh >> 4, h = bh & 15;
    int l0 = blockIdx.x * 32, d0 = blockIdx.y * 32;
    for (int i = threadIdx.y; i < 32; i += 8)
        t[i][threadIdx.x] = V[(size_t)(b * LL + l0 + i) * DD + h * DKK + d0 + threadIdx.x];
    __syncthreads();
    for (int i = threadIdx.y; i < 32; i += 8) {
        float x = t[threadIdx.x][i];
        fp16 hh, ll; hsplit(x, hh, ll);
        size_t o = ((size_t)bh * DKK + d0 + i) * LL + l0 + threadIdx.x;
        hi[o] = hh; lo[o] = ll;
    }
}

// ---------------- qrel[b,l,h,r] = Qh[b,l,h,:] . rel_k[r,:] --------------------
__global__ void qrel_kernel(const fp16* __restrict__ Q, const float* __restrict__ rel_k,
                            float* __restrict__ qrel)
{
    __shared__ float rk[NREL * DKK];
    int t = threadIdx.x;
    for (int i = t; i < NREL * DKK; i += 256) rk[i] = rel_k[i];
    __syncthreads();
    int w = t >> 5, lane = t & 31;
    int item = blockIdx.x * 8 + w;
    int bl = item >> 4, h = item & 15;
    size_t i0 = (size_t)bl * DD + h * DKK + lane * 2;
    float q0 = __half2float(Q[i0]);
    float q1 = __half2float(Q[i0 + 1]);
    for (int r = 0; r < NREL; r++) {
        float v = q0 * rk[r * DKK + lane * 2] + q1 * rk[r * DKK + lane * 2 + 1];
        v += __shfl_xor_sync(0xffffffffu, v, 16);
        v += __shfl_xor_sync(0xffffffffu, v, 8);
        v += __shfl_xor_sync(0xffffffffu, v, 4);
        v += __shfl_xor_sync(0xffffffffu, v, 2);
        v += __shfl_xor_sync(0xffffffffu, v, 1);
        if (lane == 0) qrel[(size_t)item * NREL + r] = v;
    }
}

// ---------------- residual add + layernorm (+ optional fp16 out) --------------
__global__ void ln_kernel(const float* __restrict__ X, const float* __restrict__ R,
                          const float* __restrict__ g, const float* __restrict__ be,
                          float* __restrict__ out, fp16* __restrict__ oh)
{
    int row = blockIdx.x, t = threadIdx.x;
    __shared__ float red[256];
    float v[4];
    float s1 = 0.f;
#pragma unroll
    for (int i = 0; i < 4; i++) {
        int c = t + 256 * i;
        v[i] = X[(size_t)row * DD + c] + R[(size_t)row * DD + c];
        s1 += v[i];
    }
    red[t] = s1; __syncthreads();
    for (int s = 128; s > 0; s >>= 1) { if (t < s) red[t] += red[t + s]; __syncthreads(); }
    float mu = red[0] * (1.f / 1024.f);
    __syncthreads();
    float s2 = 0.f;
#pragma unroll
    for (int i = 0; i < 4; i++) { float d = v[i] - mu; s2 += d * d; }
    red[t] = s2; __syncthreads();
    for (int s = 128; s > 0; s >>= 1) { if (t < s) red[t] += red[t + s]; __syncthreads(); }
    float rstd = rsqrtf(red[0] * (1.f / 1024.f) + 1e-6f);
#pragma unroll
    for (int i = 0; i < 4; i++) {
        int c = t + 256 * i;
        float y = (v[i] - mu) * rstd * g[c] + be[c];
        out[(size_t)row * DD + c] = y;
        if (oh) oh[(size_t)row * DD + c] = __float2half_rn(y);
    }
}

// ---------------- launch ------------------------------------------------------
extern "C" void kernel_launch(void* const* d_in, const int* in_sizes, int n_in,
                              void* d_out, int out_size)
{
    const float* q    = (const float*)d_in[0];
    const float* k    = (const float*)d_in[1];
    const float* v    = (const float*)d_in[2];
    const float* wq   = (const float*)d_in[3];
    const float* bq   = (const float*)d_in[4];
    const float* wk   = (const float*)d_in[5];
    const float* bk   = (const float*)d_in[6];
    const float* wv   = (const float*)d_in[7];
    const float* bv   = (const float*)d_in[8];
    const float* wfc  = (const float*)d_in[9];
    const float* bfc  = (const float*)d_in[10];
    const float* w1   = (const float*)d_in[11];
    const float* b1   = (const float*)d_in[12];
    const float* w2   = (const float*)d_in[13];
    const float* b2   = (const float*)d_in[14];
    const float* ln_g = (const float*)d_in[15];
    const float* ln_b = (const float*)d_in[16];
    const float* rel_k= (const float*)d_in[17];
    const float* rel_v= (const float*)d_in[18];
    float* out = (float*)d_out;

    float *gV, *gqrel, *gfc, *gx1, *gy;
    cudaGetSymbolAddress((void**)&gV, g_V);
    cudaGetSymbolAddress((void**)&gqrel, g_qrel);
    cudaGetSymbolAddress((void**)&gfc, g_fc);
    cudaGetSymbolAddress((void**)&gx1, g_x1);
    cudaGetSymbolAddress((void**)&gy, g_y);

    fp16 *wqt_h,*wqt_l,*wkt_h,*wkt_l,*wvt_h,*wvt_l,*wft_h,*wft_l,*w1t_h,*w1t_l,*w2t_h,*w2t_l;
    fp16 *qs,*ks,*vs,*Qs,*Kb_h,*Kb_l,*Vt_h,*Vt_l,*AT,*x1s,*hid;
    cudaGetSymbolAddress((void**)&wqt_h, g_wqt_h); cudaGetSymbolAddress((void**)&wqt_l, g_wqt_l);
    cudaGetSymbolAddress((void**)&wkt_h, g_wkt_h); cudaGetSymbolAddress((void**)&wkt_l, g_wkt_l);
    cudaGetSymbolAddress((void**)&wvt_h, g_wvt_h); cudaGetSymbolAddress((void**)&wvt_l, g_wvt_l);
    cudaGetSymbolAddress((void**)&wft_h, g_wft_h); cudaGetSymbolAddress((void**)&wft_l, g_wft_l);
    cudaGetSymbolAddress((void**)&w1t_h, g_w1t_h); cudaGetSymbolAddress((void**)&w1t_l, g_w1t_l);
    cudaGetSymbolAddress((void**)&w2t_h, g_w2t_h); cudaGetSymbolAddress((void**)&w2t_l, g_w2t_l);
    cudaGetSymbolAddress((void**)&qs, g_qs);
    cudaGetSymbolAddress((void**)&ks, g_ks);
    cudaGetSymbolAddress((void**)&vs, g_vs);
    cudaGetSymbolAddress((void**)&Qs, g_Qs);
    cudaGetSymbolAddress((void**)&Kb_h, g_Kb_h);   cudaGetSymbolAddress((void**)&Kb_l, g_Kb_l);
    cudaGetSymbolAddress((void**)&Vt_h, g_Vt_h);   cudaGetSymbolAddress((void**)&Vt_l, g_Vt_l);
    cudaGetSymbolAddress((void**)&AT, g_AT);
    cudaGetSymbolAddress((void**)&x1s, g_x1s);
    cudaGetSymbolAddress((void**)&hid, g_hid);

    const int SMG = 3 * 30720;       // 92160 B per CTA (2 CTAs/SM)
    const int SMFLASH = 205568;
    cudaFuncSetAttribute(hgemm<0,0>, cudaFuncAttributeMaxDynamicSharedMemorySize, SMG);
    cudaFuncSetAttribute(hgemm<0,1>, cudaFuncAttributeMaxDynamicSharedMemorySize, SMG);
    cudaFuncSetAttribute(hgemm<0,2>, cudaFuncAttributeMaxDynamicSharedMemorySize, SMG);
    cudaFuncSetAttribute(hgemm<1,1>, cudaFuncAttributeMaxDynamicSharedMemorySize, SMG);
    cudaFuncSetAttribute(flash_kernel, cudaFuncAttributeMaxDynamicSharedMemorySize, SMFLASH);

    // launches 0-4: prep (so launch #5 = Q-proj GEMM lands under ncu -s 5)
    split3_kernel<<<dim3(MTOK*DD/1024, 3), 256>>>(q, k, v, qs, ks, vs);
    convert_wt_kernel<<<dim3(32,32),  dim3(32,8)>>>(wq,  wqt_h, wqt_l, DD, DD);
    convert_wt_kernel<<<dim3(32,32),  dim3(32,8)>>>(wk,  wkt_h, wkt_l, DD, DD);
    convert_wt_kernel<<<dim3(32,32),  dim3(32,8)>>>(wv,  wvt_h, wvt_l, DD, DD);
    convert_wt_kernel<<<dim3(32,32),  dim3(32,8)>>>(wfc, wft_h, wft_l, DD, DD);

    // projections (launch #5,6,7)
    hgemm<0,1><<<dim3(8,64),256,SMG>>>(qs, wqt_h, wqt_l, bq, nullptr, Qs, nullptr, nullptr, DD, DD, DD, DD);
    hgemm<0,2><<<dim3(8,64),256,SMG>>>(ks, wkt_h, wkt_l, bk, nullptr, nullptr, Kb_h, Kb_l, DD, DD, DD, DD);
    hgemm<0,0><<<dim3(8,64),256,SMG>>>(vs, wvt_h, wvt_l, bv, gV, nullptr, nullptr, nullptr, DD, DD, DD, DD);

    // remaining weight converts + V repack + qrel
    convert_wt_kernel<<<dim3(128,32), dim3(32,8)>>>(w1, w1t_h, w1t_l, DD, DI);
    convert_wt_kernel<<<dim3(32,128), dim3(32,8)>>>(w2, w2t_h, w2t_l, DI, DD);
    transpose_split_v<<<dim3(32,2,BB*HH), dim3(32,8)>>>(gV, Vt_h, Vt_l);
    qrel_kernel<<<MTOK*HH/8, 256>>>(Qs, rel_k, gqrel);

    // fused attention -> AT (plain fp16)
    flash_kernel<<<dim3(8, BB*HH), 256, SMFLASH>>>(
        Qs, Kb_h, Kb_l, Vt_h, Vt_l, gqrel, rel_v, AT);

    // fc + residual(q) + LN
    hgemm<0,0><<<dim3(8,64),256,SMG>>>(AT, wft_h, wft_l, bfc, gfc, nullptr, nullptr, nullptr, DD, DD, DD, DD);
    ln_kernel<<<MTOK,256>>>(gfc, q, ln_g, ln_b, gx1, x1s);

    // FFN + residual + LN -> out
    hgemm<1,1><<<dim3(32,64),256,SMG>>>(x1s, w1t_h, w1t_l, b1, nullptr, hid, nullptr, nullptr, DD, DD, DD, DI);
    hgemm<0,0><<<dim3(8,64),256,SMG>>>(hid, w2t_h, w2t_l, b2, gy, nullptr, nullptr, nullptr, DI, DI, DI, DD);
    ln_kernel<<<MTOK,256>>>(gy, gx1, ln_g, ln_b, out, nullptr);
}